// round 2
// baseline (speedup 1.0000x reference)
#include <cuda_runtime.h>
#include <math.h>
#include <stdint.h>

#define Bq   32
#define Tt   512
#define FDim 256
#define NH   1024
#define NC   512
#define G4   2048      // 4*NC
#define NOUT 8
#define MT   (Bq*Tt)   // 16384 rows

// ---------------- device scratch (static: no allocation allowed) ----------------
__device__ float g_h1[(size_t)MT*NH];          // 64 MB
__device__ float g_h2[(size_t)MT*NH];          // 64 MB
__device__ float g_xp[(size_t)2*MT*G4];        // 256 MB  [dir][t][gate*NC+j][b]
__device__ float g_l0[(size_t)MT*2*NC];        // 64 MB   lstm layer0 out [b][t][2NC]
__device__ float g_l1[(size_t)MT*2*NC];        // 64 MB   lstm layer1 out
__device__ float g_hst[2][2][NC*Bq];           // [parity][dir][j*B+b]
__device__ float g_sc[Bq*Tt];
__device__ float g_pooled[Bq*2*NC];
__device__ unsigned g_bar_arrive;
__device__ volatile unsigned g_bar_gen;

// ---------------- grid barrier (all 128 blocks co-resident) ----------------
__device__ __forceinline__ void gridbar(unsigned nb, unsigned &gen) {
    __syncthreads();
    if (threadIdx.x == 0) {
        __threadfence();
        gen++;
        unsigned prev = atomicAdd(&g_bar_arrive, 1u);
        if (prev == nb * gen - 1u) {
            __threadfence();
            g_bar_gen = gen;
        } else {
            while (g_bar_gen < gen) { __nanosleep(32); }
        }
    }
    __syncthreads();
}

__global__ void reset_bar_kernel() {
    g_bar_arrive = 0u;
    g_bar_gen = 0u;
}

// ---------------- generic GEMM: C = A[M,K] * W[N,K]^T + bias1 (+bias2) ----------------
// mode 0: C[m*N+n]
// mode 1: m=(b*T+t) -> C[(t*N+n)*Bq + b]   (transposed gate layout for LSTM xp)
__global__ __launch_bounds__(256) void gemm_bias_kernel(
    const float* __restrict__ A, const float* __restrict__ W,
    const float* __restrict__ bias1, const float* __restrict__ bias2,
    float* __restrict__ C, int M, int N, int K, int mode)
{
    __shared__ float As[8 * 128];
    __shared__ float Ws[8 * 128];
    const int tid = threadIdx.x;
    const int m0 = blockIdx.y * 128;
    const int n0 = blockIdx.x * 128;
    const int tx = tid & 15;        // col group
    const int ty = tid >> 4;        // row group

    float acc[8][8];
#pragma unroll
    for (int i = 0; i < 8; i++)
#pragma unroll
        for (int j = 0; j < 8; j++) acc[i][j] = 0.f;

    const int lr = tid >> 1;          // 0..127
    const int lc = (tid & 1) * 4;     // 0 or 4
    const float* Ag = A + (size_t)(m0 + lr) * K + lc;
    const float* Wg = W + (size_t)(n0 + lr) * K + lc;

    for (int k0 = 0; k0 < K; k0 += 8) {
        float4 av = *(const float4*)(Ag + k0);
        float4 wv = *(const float4*)(Wg + k0);
        As[(lc + 0) * 128 + lr] = av.x;
        As[(lc + 1) * 128 + lr] = av.y;
        As[(lc + 2) * 128 + lr] = av.z;
        As[(lc + 3) * 128 + lr] = av.w;
        Ws[(lc + 0) * 128 + lr] = wv.x;
        Ws[(lc + 1) * 128 + lr] = wv.y;
        Ws[(lc + 2) * 128 + lr] = wv.z;
        Ws[(lc + 3) * 128 + lr] = wv.w;
        __syncthreads();
#pragma unroll
        for (int kk = 0; kk < 8; kk++) {
            float ra[8], rb[8];
            *(float4*)&ra[0] = *(const float4*)&As[kk * 128 + ty * 8];
            *(float4*)&ra[4] = *(const float4*)&As[kk * 128 + ty * 8 + 4];
            *(float4*)&rb[0] = *(const float4*)&Ws[kk * 128 + tx * 8];
            *(float4*)&rb[4] = *(const float4*)&Ws[kk * 128 + tx * 8 + 4];
#pragma unroll
            for (int i = 0; i < 8; i++)
#pragma unroll
                for (int j = 0; j < 8; j++)
                    acc[i][j] = fmaf(ra[i], rb[j], acc[i][j]);
        }
        __syncthreads();
    }

#pragma unroll
    for (int i = 0; i < 8; i++) {
        const int m = m0 + ty * 8 + i;
        const int bq = m >> 9;        // m / T
        const int t  = m & 511;       // m % T
#pragma unroll
        for (int j = 0; j < 8; j++) {
            const int n = n0 + tx * 8 + j;
            float bb = bias1[n];
            if (bias2) bb += bias2[n];
            const float v = acc[i][j] + bb;
            if (mode == 0) C[(size_t)m * N + n] = v;
            else           C[((size_t)t * N + n) * Bq + bq] = v;
        }
    }
}

// ---------------- LayerNorm + LeakyReLU (+ optional pad mask), row = 1024 ----------------
__global__ __launch_bounds__(256) void ln_lrelu_kernel(
    float* __restrict__ X, const float* __restrict__ gm, const float* __restrict__ bt,
    const int* __restrict__ lens, int domask)
{
    const int row = blockIdx.x;
    const int tid = threadIdx.x;
    float4* Xr = (float4*)(X + (size_t)row * NH);
    float4 v = Xr[tid];
    __shared__ float rs[256], rq[256];
    rs[tid] = v.x + v.y + v.z + v.w;
    rq[tid] = v.x * v.x + v.y * v.y + v.z * v.z + v.w * v.w;
    __syncthreads();
    for (int o = 128; o; o >>= 1) {
        if (tid < o) { rs[tid] += rs[tid + o]; rq[tid] += rq[tid + o]; }
        __syncthreads();
    }
    const float mean = rs[0] * (1.f / NH);
    const float var  = rq[0] * (1.f / NH) - mean * mean;
    const float rstd = rsqrtf(var + 1e-5f);
    float mul = 1.f;
    if (domask) {
        const int b = row >> 9, t = row & 511;
        if (t >= lens[b]) mul = 0.f;
    }
    const int gb = tid * 4;
    float y0 = (v.x - mean) * rstd * gm[gb + 0] + bt[gb + 0];
    float y1 = (v.y - mean) * rstd * gm[gb + 1] + bt[gb + 1];
    float y2 = (v.z - mean) * rstd * gm[gb + 2] + bt[gb + 2];
    float y3 = (v.w - mean) * rstd * gm[gb + 3] + bt[gb + 3];
    y0 = (y0 >= 0.f ? y0 : 0.01f * y0) * mul;
    y1 = (y1 >= 0.f ? y1 : 0.01f * y1) * mul;
    y2 = (y2 >= 0.f ? y2 : 0.01f * y2) * mul;
    y3 = (y3 >= 0.f ? y3 : 0.01f * y3) * mul;
    Xr[tid] = make_float4(y0, y1, y2, y3);
}

// ---------------- persistent bidirectional LSTM layer ----------------
// grid = 128 blocks x 256 threads; u = blk*256+tid; d=u>>14; j=(u&16383)>>5; b=u&31.
// smem: w_s[8j][4g][512k] (loaded once) + h_s[512k][32b] (staged per step).
__global__ __launch_bounds__(256) void lstm_layer_kernel(
    const float* __restrict__ xp,    // [2][T][G4][B]
    const float* __restrict__ whh,   // [2][G4][NC] for this layer
    float* __restrict__ out)         // [B][T][2*NC]
{
    extern __shared__ float sm[];
    float* w_s = sm;            // 16384 floats
    float* h_s = sm + 16384;    // 16384 floats

    const int tid = threadIdx.x;
    const unsigned u = blockIdx.x * 256u + tid;
    const int d  = (int)(u >> 14);
    const int r  = (int)(u & 16383u);
    const int j  = r >> 5;
    const int b  = r & 31;
    const int jl = tid >> 5;       // 0..7
    const int j0 = j - jl;

    const float* whd = whh + (size_t)d * G4 * NC;
    // stage recurrent weights once (stays resident all 512 steps)
    for (int i = tid; i < 4096; i += 256) {
        const int rowl = i >> 7, k4 = i & 127;
        const int jj = rowl >> 2, gg = rowl & 3;
        const int grow = gg * NC + j0 + jj;
        ((float4*)w_s)[i] = *((const float4*)(whd + (size_t)grow * NC) + k4);
    }
    __syncthreads();

    const float* xpd = xp + (size_t)d * Tt * G4 * Bq;
    const float* wi = w_s + (jl * 4 + 0) * 512;
    const float* wf = w_s + (jl * 4 + 1) * 512;
    const float* wg = w_s + (jl * 4 + 2) * 512;
    const float* wo = w_s + (jl * 4 + 3) * 512;

    float c = 0.f;
    unsigned gen = 0;

    for (int t = 0; t < Tt; t++) {
        const int tt = d ? (Tt - 1 - t) : t;
        if (t > 0) {
            const float4* hsrc = (const float4*)g_hst[t & 1][d];
            for (int i = tid; i < 4096; i += 256)
                ((float4*)h_s)[i] = __ldcg(hsrc + i);
        }
        __syncthreads();

        const size_t xbase = ((size_t)tt * G4 + j) * Bq + b;
        float ai = __ldg(xpd + xbase);
        float af = __ldg(xpd + xbase + (size_t)NC * Bq);
        float ag = __ldg(xpd + xbase + (size_t)2 * NC * Bq);
        float ao = __ldg(xpd + xbase + (size_t)3 * NC * Bq);

        if (t > 0) {
#pragma unroll 4
            for (int k4 = 0; k4 < 128; k4++) {
                const float4 w4i = ((const float4*)wi)[k4];
                const float4 w4f = ((const float4*)wf)[k4];
                const float4 w4g = ((const float4*)wg)[k4];
                const float4 w4o = ((const float4*)wo)[k4];
                const int kb = k4 * 128 + b;
                const float h0 = h_s[kb];
                const float h1 = h_s[kb + 32];
                const float h2 = h_s[kb + 64];
                const float h3 = h_s[kb + 96];
                ai = fmaf(w4i.x, h0, ai); ai = fmaf(w4i.y, h1, ai);
                ai = fmaf(w4i.z, h2, ai); ai = fmaf(w4i.w, h3, ai);
                af = fmaf(w4f.x, h0, af); af = fmaf(w4f.y, h1, af);
                af = fmaf(w4f.z, h2, af); af = fmaf(w4f.w, h3, af);
                ag = fmaf(w4g.x, h0, ag); ag = fmaf(w4g.y, h1, ag);
                ag = fmaf(w4g.z, h2, ag); ag = fmaf(w4g.w, h3, ag);
                ao = fmaf(w4o.x, h0, ao); ao = fmaf(w4o.y, h1, ao);
                ao = fmaf(w4o.z, h2, ao); ao = fmaf(w4o.w, h3, ao);
            }
        }
        const float si = 1.f / (1.f + expf(-ai));
        const float sf = 1.f / (1.f + expf(-af));
        const float sg = tanhf(ag);
        const float so = 1.f / (1.f + expf(-ao));
        c = sf * c + si * sg;
        const float h = so * tanhf(c);

        __stcg(&g_hst[(t + 1) & 1][d][j * Bq + b], h);
        out[((size_t)b * Tt + tt) * (2 * NC) + d * NC + j] = h;

        gridbar(gridDim.x, gen);
    }
}

// ---------------- attention scores: warp per (b,t) ----------------
__global__ __launch_bounds__(256) void scores_kernel(
    const float* __restrict__ h, const float* __restrict__ wu,
    const float* __restrict__ bu, const int* __restrict__ lens,
    float* __restrict__ sc)
{
    const int gid = blockIdx.x * 256 + threadIdx.x;
    const int w = gid >> 5, lane = gid & 31;
    const float* hr = h + (size_t)w * (2 * NC);
    float s = 0.f;
    for (int i = lane; i < 2 * NC; i += 32) s = fmaf(hr[i], wu[i], s);
#pragma unroll
    for (int o = 16; o; o >>= 1) s += __shfl_xor_sync(0xffffffffu, s, o);
    if (lane == 0) {
        const int b = w >> 9, t = w & 511;
        sc[w] = (t < lens[b]) ? (s + bu[0]) : -INFINITY;
    }
}

// ---------------- masked softmax + weighted pool, block per batch ----------------
__global__ __launch_bounds__(256) void softpool_kernel(
    const float* __restrict__ h, const float* __restrict__ sc,
    float* __restrict__ pooled)
{
    const int b = blockIdx.x, tid = threadIdx.x;
    __shared__ float al[512];
    __shared__ float red[256];
    float m = -INFINITY;
    for (int t = tid; t < 512; t += 256) m = fmaxf(m, sc[b * 512 + t]);
    red[tid] = m; __syncthreads();
    for (int o = 128; o; o >>= 1) {
        if (tid < o) red[tid] = fmaxf(red[tid], red[tid + o]);
        __syncthreads();
    }
    m = red[0]; __syncthreads();
    float s = 0.f;
    for (int t = tid; t < 512; t += 256) {
        const float e = expf(sc[b * 512 + t] - m);
        al[t] = e; s += e;
    }
    red[tid] = s; __syncthreads();
    for (int o = 128; o; o >>= 1) {
        if (tid < o) red[tid] += red[tid + o];
        __syncthreads();
    }
    const float inv = 1.f / red[0];
    __syncthreads();
    for (int d2 = tid; d2 < 2 * NC; d2 += 256) {
        float acc = 0.f;
        for (int t = 0; t < 512; t++)
            acc = fmaf(al[t], h[((size_t)b * 512 + t) * (2 * NC) + d2], acc);
        pooled[b * (2 * NC) + d2] = acc * inv;
    }
}

// ---------------- final classifier: 32x8 outputs ----------------
__global__ __launch_bounds__(256) void final_kernel(
    const float* __restrict__ pooled, const float* __restrict__ Wc,
    const float* __restrict__ bc, float* __restrict__ out)
{
    const int tid = threadIdx.x;
    const int b = tid >> 3, o = tid & 7;
    const float* p = pooled + b * (2 * NC);
    const float* w = Wc + o * (2 * NC);
    float acc = bc[o];
    for (int k = 0; k < 2 * NC; k++) acc = fmaf(p[k], w[k], acc);
    out[b * NOUT + o] = acc;
}

// ---------------- launch ----------------
extern "C" void kernel_launch(void* const* d_in, const int* in_sizes, int n_in,
                              void* d_out, int out_size)
{
    const float* x    = (const float*)d_in[0];
    const int*   lens = (const int*)  d_in[1];
    const float* W1   = (const float*)d_in[2];
    const float* b1   = (const float*)d_in[3];
    const float* g1   = (const float*)d_in[4];
    const float* be1  = (const float*)d_in[5];
    const float* W2   = (const float*)d_in[6];
    const float* b2   = (const float*)d_in[7];
    const float* g2   = (const float*)d_in[8];
    const float* be2  = (const float*)d_in[9];
    const float* wih  = (const float*)d_in[10];
    const float* whh  = (const float*)d_in[11];
    const float* bih  = (const float*)d_in[12];
    const float* bhh  = (const float*)d_in[13];
    const float* wu   = (const float*)d_in[14];
    const float* bu   = (const float*)d_in[15];
    const float* Wc   = (const float*)d_in[16];
    const float* bc   = (const float*)d_in[17];
    float* out = (float*)d_out;

    float *h1, *h2, *xpb, *l0, *l1, *sc, *pooled;
    cudaGetSymbolAddress((void**)&h1, g_h1);
    cudaGetSymbolAddress((void**)&h2, g_h2);
    cudaGetSymbolAddress((void**)&xpb, g_xp);
    cudaGetSymbolAddress((void**)&l0, g_l0);
    cudaGetSymbolAddress((void**)&l1, g_l1);
    cudaGetSymbolAddress((void**)&sc, g_sc);
    cudaGetSymbolAddress((void**)&pooled, g_pooled);

    cudaFuncSetAttribute(lstm_layer_kernel,
                         cudaFuncAttributeMaxDynamicSharedMemorySize, 131072);

    // MLP
    gemm_bias_kernel<<<dim3(NH / 128, MT / 128), 256>>>(x, W1, b1, nullptr, h1, MT, NH, FDim, 0);
    ln_lrelu_kernel<<<MT, 256>>>(h1, g1, be1, nullptr, 0);
    gemm_bias_kernel<<<dim3(NH / 128, MT / 128), 256>>>(h1, W2, b2, nullptr, h2, MT, NH, NH, 0);
    ln_lrelu_kernel<<<MT, 256>>>(h2, g2, be2, lens, 1);

    // 2 bidirectional LSTM layers
    const float* lin = h2;
    float* louts[2] = { l0, l1 };
    for (int l = 0; l < 2; l++) {
        for (int dd = 0; dd < 2; dd++) {
            gemm_bias_kernel<<<dim3(G4 / 128, MT / 128), 256>>>(
                lin, wih + (size_t)(l * 2 + dd) * G4 * NH,
                bih + (size_t)(l * 2 + dd) * G4, bhh + (size_t)(l * 2 + dd) * G4,
                xpb + (size_t)dd * MT * G4, MT, G4, NH, 1);
        }
        reset_bar_kernel<<<1, 1>>>();
        lstm_layer_kernel<<<128, 256, 131072>>>(xpb, whh + (size_t)l * 2 * G4 * NC, louts[l]);
        lin = louts[l];
    }

    // attention + head
    scores_kernel<<<MT / 8, 256>>>(l1, wu, bu, lens, sc);
    softpool_kernel<<<Bq, 256>>>(l1, sc, pooled);
    final_kernel<<<1, 256>>>(pooled, Wc, bc, out);
}

// round 3
// speedup vs baseline: 1.2756x; 1.2756x over previous
#include <cuda_runtime.h>
#include <math.h>
#include <stdint.h>

#define Bq   32
#define Tt   512
#define FDim 256
#define NH   1024
#define NC   512
#define G4   2048      // 4*NC
#define NOUT 8
#define MT   (Bq*Tt)   // 16384 rows

// ---------------- device scratch (static: no allocation allowed) ----------------
__device__ float g_h1[(size_t)MT*NH];
__device__ float g_h2[(size_t)MT*NH];
__device__ float g_xp[(size_t)2*MT*G4];        // [dir][t][gate*NC+j][b]
__device__ float g_l0[(size_t)MT*2*NC];
__device__ float g_l1[(size_t)MT*2*NC];
__device__ float g_hst[2][2][NC*Bq];           // [parity][dir][j*B+b]
__device__ float g_sc[Bq*Tt];
__device__ float g_pooled[Bq*2*NC];
__device__ unsigned g_bar_arrive;
__device__ volatile unsigned g_bar_gen;

// ---------------- grid barrier ----------------
__device__ __forceinline__ void gridbar(unsigned nb, unsigned &gen) {
    __syncthreads();
    if (threadIdx.x == 0) {
        __threadfence();
        gen++;
        unsigned prev = atomicAdd(&g_bar_arrive, 1u);
        if (prev == nb * gen - 1u) {
            __threadfence();
            g_bar_gen = gen;
        } else {
            while (g_bar_gen < gen) { __nanosleep(32); }
        }
    }
    __syncthreads();
}

__global__ void reset_bar_kernel() {
    g_bar_arrive = 0u;
    g_bar_gen = 0u;
}

// ---------------- tf32 mma helpers ----------------
__device__ __forceinline__ unsigned su32(const void* p) {
    unsigned r;
    asm("{.reg .u64 t; cvta.to.shared.u64 t, %1; cvt.u32.u64 %0, t;}" : "=r"(r) : "l"(p));
    return r;
}
__device__ __forceinline__ void cp16(unsigned s, const void* g) {
    asm volatile("cp.async.cg.shared.global [%0], [%1], 16;\n" :: "r"(s), "l"(g));
}
__device__ __forceinline__ uint32_t tf32rn(float x) {
    uint32_t r;
    asm("cvt.rna.tf32.f32 %0, %1;\n" : "=r"(r) : "f"(x));
    return r;
}
__device__ __forceinline__ void mma_tf32(float (&c)[4], const uint32_t (&a)[4], const uint32_t (&b)[2]) {
    asm volatile("mma.sync.aligned.m16n8k8.row.col.f32.tf32.tf32.f32 "
        "{%0,%1,%2,%3}, {%4,%5,%6,%7}, {%8,%9}, {%0,%1,%2,%3};\n"
        : "+f"(c[0]), "+f"(c[1]), "+f"(c[2]), "+f"(c[3])
        : "r"(a[0]), "r"(a[1]), "r"(a[2]), "r"(a[3]), "r"(b[0]), "r"(b[1]));
}

// ---------------- tf32 GEMM: C = A[M,K] * W[N,K]^T + bias1 (+bias2) ----------------
// mode 0: C[m*N+n]
// mode 1: m=(b*T+t) -> C[(t*N+n)*Bq + b]
#define PADK 20
__global__ __launch_bounds__(256) void gemm_tf32_kernel(
    const float* __restrict__ A, const float* __restrict__ W,
    const float* __restrict__ bias1, const float* __restrict__ bias2,
    float* __restrict__ C, int M, int N, int K, int mode)
{
    __shared__ float As[2][128 * PADK];
    __shared__ float Ws[2][128 * PADK];
    const int tid  = threadIdx.x;
    const int warp = tid >> 5, lane = tid & 31;
    const int wm = warp & 3, wn = warp >> 2;        // 4 x 2 warp grid
    const int qr = lane >> 2, qk = lane & 3;
    const int m0 = blockIdx.y * 128;
    const int n0 = blockIdx.x * 128;

    // each thread stages 2 x 16B chunks of A and of W per stage
    const int ca = tid * 2, cb = ca + 1;
    const int ra = ca >> 2, ka = (ca & 3) * 4;
    const int rb = cb >> 2, kb = (cb & 3) * 4;

    const float* Ag = A + (size_t)m0 * K;
    const float* Wg = W + (size_t)n0 * K;

    const unsigned sAa = su32(&As[0][ra * PADK + ka]);
    const unsigned sAb = su32(&As[0][rb * PADK + kb]);
    const unsigned sWa = su32(&Ws[0][ra * PADK + ka]);
    const unsigned sWb = su32(&Ws[0][rb * PADK + kb]);
    const unsigned stgB = 128 * PADK * 4;  // stage stride (bytes)

    float acc[2][8][4];
#pragma unroll
    for (int i = 0; i < 2; i++)
#pragma unroll
        for (int j = 0; j < 8; j++)
#pragma unroll
            for (int l = 0; l < 4; l++) acc[i][j][l] = 0.f;

    const int nk = K >> 4;

    // prologue: stage 0
    cp16(sAa, Ag + (size_t)ra * K + ka);
    cp16(sAb, Ag + (size_t)rb * K + kb);
    cp16(sWa, Wg + (size_t)ra * K + ka);
    cp16(sWb, Wg + (size_t)rb * K + kb);
    asm volatile("cp.async.commit_group;\n");

    for (int kt = 0; kt < nk; kt++) {
        if (kt + 1 < nk) {
            const int k0 = (kt + 1) * 16;
            const unsigned so = ((kt + 1) & 1) * stgB;
            cp16(sAa + so, Ag + (size_t)ra * K + k0 + ka);
            cp16(sAb + so, Ag + (size_t)rb * K + k0 + kb);
            cp16(sWa + so, Wg + (size_t)ra * K + k0 + ka);
            cp16(sWb + so, Wg + (size_t)rb * K + k0 + kb);
            asm volatile("cp.async.commit_group;\n");
            asm volatile("cp.async.wait_group 1;\n");
        } else {
            asm volatile("cp.async.wait_group 0;\n");
        }
        __syncthreads();

        const float* Ab_ = &As[kt & 1][0];
        const float* Bb_ = &Ws[kt & 1][0];
#pragma unroll
        for (int ks = 0; ks < 16; ks += 8) {
            uint32_t a[2][4];
#pragma unroll
            for (int mt = 0; mt < 2; mt++) {
                const float* ap = Ab_ + (wm * 32 + mt * 16 + qr) * PADK + ks + qk;
                a[mt][0] = tf32rn(ap[0]);
                a[mt][1] = tf32rn(ap[8 * PADK]);
                a[mt][2] = tf32rn(ap[4]);
                a[mt][3] = tf32rn(ap[8 * PADK + 4]);
            }
#pragma unroll
            for (int nt = 0; nt < 8; nt++) {
                const float* bp = Bb_ + (wn * 64 + nt * 8 + qr) * PADK + ks + qk;
                uint32_t b[2];
                b[0] = tf32rn(bp[0]);
                b[1] = tf32rn(bp[4]);
                mma_tf32(acc[0][nt], a[0], b);
                mma_tf32(acc[1][nt], a[1], b);
            }
        }
        __syncthreads();
    }

    // epilogue
#pragma unroll
    for (int mt = 0; mt < 2; mt++) {
        const int mr = m0 + wm * 32 + mt * 16 + qr;
#pragma unroll
        for (int nt = 0; nt < 8; nt++) {
            const int n = n0 + wn * 64 + nt * 8 + qk * 2;
            float b0 = bias1[n], b1 = bias1[n + 1];
            if (bias2) { b0 += bias2[n]; b1 += bias2[n + 1]; }
            const float v00 = acc[mt][nt][0] + b0, v01 = acc[mt][nt][1] + b1;
            const float v10 = acc[mt][nt][2] + b0, v11 = acc[mt][nt][3] + b1;
            if (mode == 0) {
                *(float2*)&C[(size_t)mr * N + n]       = make_float2(v00, v01);
                *(float2*)&C[(size_t)(mr + 8) * N + n] = make_float2(v10, v11);
            } else {
                const int bq0 = mr >> 9, t0 = mr & 511;
                const int bq1 = (mr + 8) >> 9, t1 = (mr + 8) & 511;
                C[((size_t)t0 * N + n) * Bq + bq0]     = v00;
                C[((size_t)t0 * N + n + 1) * Bq + bq0] = v01;
                C[((size_t)t1 * N + n) * Bq + bq1]     = v10;
                C[((size_t)t1 * N + n + 1) * Bq + bq1] = v11;
            }
        }
    }
}

// ---------------- LayerNorm + LeakyReLU (+ optional pad mask), row = 1024 ----------------
__global__ __launch_bounds__(256) void ln_lrelu_kernel(
    float* __restrict__ X, const float* __restrict__ gm, const float* __restrict__ bt,
    const int* __restrict__ lens, int domask)
{
    const int row = blockIdx.x;
    const int tid = threadIdx.x;
    float4* Xr = (float4*)(X + (size_t)row * NH);
    float4 v = Xr[tid];
    __shared__ float rs[256], rq[256];
    rs[tid] = v.x + v.y + v.z + v.w;
    rq[tid] = v.x * v.x + v.y * v.y + v.z * v.z + v.w * v.w;
    __syncthreads();
    for (int o = 128; o; o >>= 1) {
        if (tid < o) { rs[tid] += rs[tid + o]; rq[tid] += rq[tid + o]; }
        __syncthreads();
    }
    const float mean = rs[0] * (1.f / NH);
    const float var  = rq[0] * (1.f / NH) - mean * mean;
    const float rstd = rsqrtf(var + 1e-5f);
    float mul = 1.f;
    if (domask) {
        const int b = row >> 9, t = row & 511;
        if (t >= lens[b]) mul = 0.f;
    }
    const int gb = tid * 4;
    float y0 = (v.x - mean) * rstd * gm[gb + 0] + bt[gb + 0];
    float y1 = (v.y - mean) * rstd * gm[gb + 1] + bt[gb + 1];
    float y2 = (v.z - mean) * rstd * gm[gb + 2] + bt[gb + 2];
    float y3 = (v.w - mean) * rstd * gm[gb + 3] + bt[gb + 3];
    y0 = (y0 >= 0.f ? y0 : 0.01f * y0) * mul;
    y1 = (y1 >= 0.f ? y1 : 0.01f * y1) * mul;
    y2 = (y2 >= 0.f ? y2 : 0.01f * y2) * mul;
    y3 = (y3 >= 0.f ? y3 : 0.01f * y3) * mul;
    Xr[tid] = make_float4(y0, y1, y2, y3);
}

// ---------------- persistent bidirectional LSTM layer ----------------
__global__ __launch_bounds__(256) void lstm_layer_kernel(
    const float* __restrict__ xp,    // [2][T][G4][B]
    const float* __restrict__ whh,   // [2][G4][NC] for this layer
    float* __restrict__ out)         // [B][T][2*NC]
{
    extern __shared__ float sm[];
    float* w_s = sm;            // 16384 floats
    float* h_s = sm + 16384;    // 16384 floats

    const int tid = threadIdx.x;
    const unsigned u = blockIdx.x * 256u + tid;
    const int d  = (int)(u >> 14);
    const int r  = (int)(u & 16383u);
    const int j  = r >> 5;
    const int b  = r & 31;
    const int jl = tid >> 5;
    const int j0 = j - jl;

    const float* whd = whh + (size_t)d * G4 * NC;
    for (int i = tid; i < 4096; i += 256) {
        const int rowl = i >> 7, k4 = i & 127;
        const int jj = rowl >> 2, gg = rowl & 3;
        const int grow = gg * NC + j0 + jj;
        ((float4*)w_s)[i] = *((const float4*)(whd + (size_t)grow * NC) + k4);
    }
    __syncthreads();

    const float* xpd = xp + (size_t)d * Tt * G4 * Bq;
    const float* wi = w_s + (jl * 4 + 0) * 512;
    const float* wf = w_s + (jl * 4 + 1) * 512;
    const float* wg = w_s + (jl * 4 + 2) * 512;
    const float* wo = w_s + (jl * 4 + 3) * 512;

    float c = 0.f;
    unsigned gen = 0;

    for (int t = 0; t < Tt; t++) {
        const int tt = d ? (Tt - 1 - t) : t;
        if (t > 0) {
            const float4* hsrc = (const float4*)g_hst[t & 1][d];
            for (int i = tid; i < 4096; i += 256)
                ((float4*)h_s)[i] = __ldcg(hsrc + i);
        }
        __syncthreads();

        const size_t xbase = ((size_t)tt * G4 + j) * Bq + b;
        float ai = __ldg(xpd + xbase);
        float af = __ldg(xpd + xbase + (size_t)NC * Bq);
        float ag = __ldg(xpd + xbase + (size_t)2 * NC * Bq);
        float ao = __ldg(xpd + xbase + (size_t)3 * NC * Bq);

        if (t > 0) {
#pragma unroll 4
            for (int k4 = 0; k4 < 128; k4++) {
                const float4 w4i = ((const float4*)wi)[k4];
                const float4 w4f = ((const float4*)wf)[k4];
                const float4 w4g = ((const float4*)wg)[k4];
                const float4 w4o = ((const float4*)wo)[k4];
                const int kb = k4 * 128 + b;
                const float h0 = h_s[kb];
                const float h1 = h_s[kb + 32];
                const float h2 = h_s[kb + 64];
                const float h3 = h_s[kb + 96];
                ai = fmaf(w4i.x, h0, ai); ai = fmaf(w4i.y, h1, ai);
                ai = fmaf(w4i.z, h2, ai); ai = fmaf(w4i.w, h3, ai);
                af = fmaf(w4f.x, h0, af); af = fmaf(w4f.y, h1, af);
                af = fmaf(w4f.z, h2, af); af = fmaf(w4f.w, h3, af);
                ag = fmaf(w4g.x, h0, ag); ag = fmaf(w4g.y, h1, ag);
                ag = fmaf(w4g.z, h2, ag); ag = fmaf(w4g.w, h3, ag);
                ao = fmaf(w4o.x, h0, ao); ao = fmaf(w4o.y, h1, ao);
                ao = fmaf(w4o.z, h2, ao); ao = fmaf(w4o.w, h3, ao);
            }
        }
        const float si = 1.f / (1.f + expf(-ai));
        const float sf = 1.f / (1.f + expf(-af));
        const float sg = tanhf(ag);
        const float so = 1.f / (1.f + expf(-ao));
        c = sf * c + si * sg;
        const float h = so * tanhf(c);

        __stcg(&g_hst[(t + 1) & 1][d][j * Bq + b], h);
        out[((size_t)b * Tt + tt) * (2 * NC) + d * NC + j] = h;

        gridbar(gridDim.x, gen);
    }
}

// ---------------- attention scores ----------------
__global__ __launch_bounds__(256) void scores_kernel(
    const float* __restrict__ h, const float* __restrict__ wu,
    const float* __restrict__ bu, const int* __restrict__ lens,
    float* __restrict__ sc)
{
    const int gid = blockIdx.x * 256 + threadIdx.x;
    const int w = gid >> 5, lane = gid & 31;
    const float* hr = h + (size_t)w * (2 * NC);
    float s = 0.f;
    for (int i = lane; i < 2 * NC; i += 32) s = fmaf(hr[i], wu[i], s);
#pragma unroll
    for (int o = 16; o; o >>= 1) s += __shfl_xor_sync(0xffffffffu, s, o);
    if (lane == 0) {
        const int b = w >> 9, t = w & 511;
        sc[w] = (t < lens[b]) ? (s + bu[0]) : -INFINITY;
    }
}

// ---------------- masked softmax + weighted pool ----------------
__global__ __launch_bounds__(256) void softpool_kernel(
    const float* __restrict__ h, const float* __restrict__ sc,
    float* __restrict__ pooled)
{
    const int b = blockIdx.x, tid = threadIdx.x;
    __shared__ float al[512];
    __shared__ float red[256];
    float m = -INFINITY;
    for (int t = tid; t < 512; t += 256) m = fmaxf(m, sc[b * 512 + t]);
    red[tid] = m; __syncthreads();
    for (int o = 128; o; o >>= 1) {
        if (tid < o) red[tid] = fmaxf(red[tid], red[tid + o]);
        __syncthreads();
    }
    m = red[0]; __syncthreads();
    float s = 0.f;
    for (int t = tid; t < 512; t += 256) {
        const float e = expf(sc[b * 512 + t] - m);
        al[t] = e; s += e;
    }
    red[tid] = s; __syncthreads();
    for (int o = 128; o; o >>= 1) {
        if (tid < o) red[tid] += red[tid + o];
        __syncthreads();
    }
    const float inv = 1.f / red[0];
    __syncthreads();
    for (int d2 = tid; d2 < 2 * NC; d2 += 256) {
        float acc = 0.f;
        for (int t = 0; t < 512; t++)
            acc = fmaf(al[t], h[((size_t)b * 512 + t) * (2 * NC) + d2], acc);
        pooled[b * (2 * NC) + d2] = acc * inv;
    }
}

// ---------------- final classifier ----------------
__global__ __launch_bounds__(256) void final_kernel(
    const float* __restrict__ pooled, const float* __restrict__ Wc,
    const float* __restrict__ bc, float* __restrict__ out)
{
    const int tid = threadIdx.x;
    const int b = tid >> 3, o = tid & 7;
    const float* p = pooled + b * (2 * NC);
    const float* w = Wc + o * (2 * NC);
    float acc = bc[o];
    for (int k = 0; k < 2 * NC; k++) acc = fmaf(p[k], w[k], acc);
    out[b * NOUT + o] = acc;
}

// ---------------- launch ----------------
extern "C" void kernel_launch(void* const* d_in, const int* in_sizes, int n_in,
                              void* d_out, int out_size)
{
    const float* x    = (const float*)d_in[0];
    const int*   lens = (const int*)  d_in[1];
    const float* W1   = (const float*)d_in[2];
    const float* b1   = (const float*)d_in[3];
    const float* g1   = (const float*)d_in[4];
    const float* be1  = (const float*)d_in[5];
    const float* W2   = (const float*)d_in[6];
    const float* b2   = (const float*)d_in[7];
    const float* g2   = (const float*)d_in[8];
    const float* be2  = (const float*)d_in[9];
    const float* wih  = (const float*)d_in[10];
    const float* whh  = (const float*)d_in[11];
    const float* bih  = (const float*)d_in[12];
    const float* bhh  = (const float*)d_in[13];
    const float* wu   = (const float*)d_in[14];
    const float* bu   = (const float*)d_in[15];
    const float* Wc   = (const float*)d_in[16];
    const float* bc   = (const float*)d_in[17];
    float* out = (float*)d_out;

    float *h1, *h2, *xpb, *l0, *l1, *sc, *pooled;
    cudaGetSymbolAddress((void**)&h1, g_h1);
    cudaGetSymbolAddress((void**)&h2, g_h2);
    cudaGetSymbolAddress((void**)&xpb, g_xp);
    cudaGetSymbolAddress((void**)&l0, g_l0);
    cudaGetSymbolAddress((void**)&l1, g_l1);
    cudaGetSymbolAddress((void**)&sc, g_sc);
    cudaGetSymbolAddress((void**)&pooled, g_pooled);

    cudaFuncSetAttribute(lstm_layer_kernel,
                         cudaFuncAttributeMaxDynamicSharedMemorySize, 131072);

    // MLP
    gemm_tf32_kernel<<<dim3(NH / 128, MT / 128), 256>>>(x, W1, b1, nullptr, h1, MT, NH, FDim, 0);
    ln_lrelu_kernel<<<MT, 256>>>(h1, g1, be1, nullptr, 0);
    gemm_tf32_kernel<<<dim3(NH / 128, MT / 128), 256>>>(h1, W2, b2, nullptr, h2, MT, NH, NH, 0);
    ln_lrelu_kernel<<<MT, 256>>>(h2, g2, be2, lens, 1);

    // 2 bidirectional LSTM layers
    const float* lin = h2;
    float* louts[2] = { l0, l1 };
    for (int l = 0; l < 2; l++) {
        for (int dd = 0; dd < 2; dd++) {
            gemm_tf32_kernel<<<dim3(G4 / 128, MT / 128), 256>>>(
                lin, wih + (size_t)(l * 2 + dd) * G4 * NH,
                bih + (size_t)(l * 2 + dd) * G4, bhh + (size_t)(l * 2 + dd) * G4,
                xpb + (size_t)dd * MT * G4, MT, G4, NH, 1);
        }
        reset_bar_kernel<<<1, 1>>>();
        lstm_layer_kernel<<<128, 256, 131072>>>(xpb, whh + (size_t)l * 2 * G4 * NC, louts[l]);
        lin = louts[l];
    }

    // attention + head
    scores_kernel<<<MT / 8, 256>>>(l1, wu, bu, lens, sc);
    softpool_kernel<<<Bq, 256>>>(l1, sc, pooled);
    final_kernel<<<1, 256>>>(pooled, Wc, bc, out);
}

// round 4
// speedup vs baseline: 2.3869x; 1.8712x over previous
#include <cuda_runtime.h>
#include <math.h>
#include <stdint.h>

#define Bq   32
#define Tt   512
#define FDim 256
#define NH   1024
#define NC   512
#define G4   2048      // 4*NC
#define NOUT 8
#define MT   (Bq*Tt)   // 16384 rows

// ---------------- device scratch ----------------
__device__ float g_h1[(size_t)MT*NH];
__device__ float g_h2[(size_t)MT*NH];
__device__ float g_xp[(size_t)2*MT*G4];        // [dir][(b*T+t)][g]
__device__ float g_l0[(size_t)MT*2*NC];
__device__ float g_l1[(size_t)MT*2*NC];
__device__ float g_hbuf[4][Bq*NC];             // [dir*2+parity][b][j]
__device__ float g_sc[Bq*Tt];
__device__ float g_pooled[Bq*2*NC];
__device__ unsigned g_bar_arrive;
__device__ volatile unsigned g_bar_gen;

// ---------------- grid barrier ----------------
__device__ __forceinline__ void gridbar(unsigned nb, unsigned &gen) {
    __syncthreads();
    if (threadIdx.x == 0) {
        __threadfence();
        gen++;
        unsigned prev = atomicAdd(&g_bar_arrive, 1u);
        if (prev == nb * gen - 1u) {
            __threadfence();
            g_bar_gen = gen;
        } else {
            while (g_bar_gen < gen) { __nanosleep(32); }
        }
    }
    __syncthreads();
}

__global__ void reset_bar_kernel() {
    g_bar_arrive = 0u;
    g_bar_gen = 0u;
}

// ---------------- tf32 mma helpers ----------------
__device__ __forceinline__ unsigned su32(const void* p) {
    unsigned r;
    asm("{.reg .u64 t; cvta.to.shared.u64 t, %1; cvt.u32.u64 %0, t;}" : "=r"(r) : "l"(p));
    return r;
}
__device__ __forceinline__ void cp16(unsigned s, const void* g) {
    asm volatile("cp.async.cg.shared.global [%0], [%1], 16;\n" :: "r"(s), "l"(g));
}
__device__ __forceinline__ uint32_t tf32rn(float x) {
    uint32_t r;
    asm("cvt.rna.tf32.f32 %0, %1;\n" : "=r"(r) : "f"(x));
    return r;
}
__device__ __forceinline__ void mma_tf32(float (&c)[4], const uint32_t (&a)[4], const uint32_t (&b)[2]) {
    asm volatile("mma.sync.aligned.m16n8k8.row.col.f32.tf32.tf32.f32 "
        "{%0,%1,%2,%3}, {%4,%5,%6,%7}, {%8,%9}, {%0,%1,%2,%3};\n"
        : "+f"(c[0]), "+f"(c[1]), "+f"(c[2]), "+f"(c[3])
        : "r"(a[0]), "r"(a[1]), "r"(a[2]), "r"(a[3]), "r"(b[0]), "r"(b[1]));
}

// ---------------- tf32 GEMM: C = A[M,K] * W[N,K]^T + bias1 (+bias2), C[m*N+n] ----------------
#define PADK 20
__global__ __launch_bounds__(256) void gemm_tf32_kernel(
    const float* __restrict__ A, const float* __restrict__ W,
    const float* __restrict__ bias1, const float* __restrict__ bias2,
    float* __restrict__ C, int M, int N, int K)
{
    __shared__ float As[2][128 * PADK];
    __shared__ float Ws[2][128 * PADK];
    const int tid  = threadIdx.x;
    const int warp = tid >> 5, lane = tid & 31;
    const int wm = warp & 3, wn = warp >> 2;
    const int qr = lane >> 2, qk = lane & 3;
    const int m0 = blockIdx.y * 128;
    const int n0 = blockIdx.x * 128;

    const int ca = tid * 2, cb = ca + 1;
    const int ra = ca >> 2, ka = (ca & 3) * 4;
    const int rb = cb >> 2, kb = (cb & 3) * 4;

    const float* Ag = A + (size_t)m0 * K;
    const float* Wg = W + (size_t)n0 * K;

    const unsigned sAa = su32(&As[0][ra * PADK + ka]);
    const unsigned sAb = su32(&As[0][rb * PADK + kb]);
    const unsigned sWa = su32(&Ws[0][ra * PADK + ka]);
    const unsigned sWb = su32(&Ws[0][rb * PADK + kb]);
    const unsigned stgB = 128 * PADK * 4;

    float acc[2][8][4];
#pragma unroll
    for (int i = 0; i < 2; i++)
#pragma unroll
        for (int j = 0; j < 8; j++)
#pragma unroll
            for (int l = 0; l < 4; l++) acc[i][j][l] = 0.f;

    const int nk = K >> 4;

    cp16(sAa, Ag + (size_t)ra * K + ka);
    cp16(sAb, Ag + (size_t)rb * K + kb);
    cp16(sWa, Wg + (size_t)ra * K + ka);
    cp16(sWb, Wg + (size_t)rb * K + kb);
    asm volatile("cp.async.commit_group;\n");

    for (int kt = 0; kt < nk; kt++) {
        if (kt + 1 < nk) {
            const int k0 = (kt + 1) * 16;
            const unsigned so = ((kt + 1) & 1) * stgB;
            cp16(sAa + so, Ag + (size_t)ra * K + k0 + ka);
            cp16(sAb + so, Ag + (size_t)rb * K + k0 + kb);
            cp16(sWa + so, Wg + (size_t)ra * K + k0 + ka);
            cp16(sWb + so, Wg + (size_t)rb * K + k0 + kb);
            asm volatile("cp.async.commit_group;\n");
            asm volatile("cp.async.wait_group 1;\n");
        } else {
            asm volatile("cp.async.wait_group 0;\n");
        }
        __syncthreads();

        const float* Ab_ = &As[kt & 1][0];
        const float* Bb_ = &Ws[kt & 1][0];
#pragma unroll
        for (int ks = 0; ks < 16; ks += 8) {
            uint32_t a[2][4];
#pragma unroll
            for (int mt = 0; mt < 2; mt++) {
                const float* ap = Ab_ + (wm * 32 + mt * 16 + qr) * PADK + ks + qk;
                a[mt][0] = tf32rn(ap[0]);
                a[mt][1] = tf32rn(ap[8 * PADK]);
                a[mt][2] = tf32rn(ap[4]);
                a[mt][3] = tf32rn(ap[8 * PADK + 4]);
            }
#pragma unroll
            for (int nt = 0; nt < 8; nt++) {
                const float* bp = Bb_ + (wn * 64 + nt * 8 + qr) * PADK + ks + qk;
                uint32_t b[2];
                b[0] = tf32rn(bp[0]);
                b[1] = tf32rn(bp[4]);
                mma_tf32(acc[0][nt], a[0], b);
                mma_tf32(acc[1][nt], a[1], b);
            }
        }
        __syncthreads();
    }

#pragma unroll
    for (int mt = 0; mt < 2; mt++) {
        const int mr = m0 + wm * 32 + mt * 16 + qr;
#pragma unroll
        for (int nt = 0; nt < 8; nt++) {
            const int n = n0 + wn * 64 + nt * 8 + qk * 2;
            float b0 = bias1[n], b1 = bias1[n + 1];
            if (bias2) { b0 += bias2[n]; b1 += bias2[n + 1]; }
            *(float2*)&C[(size_t)mr * N + n]       = make_float2(acc[mt][nt][0] + b0, acc[mt][nt][1] + b1);
            *(float2*)&C[(size_t)(mr + 8) * N + n] = make_float2(acc[mt][nt][2] + b0, acc[mt][nt][3] + b1);
        }
    }
}

// ---------------- LayerNorm + LeakyReLU (+ optional pad mask), row = 1024 ----------------
__global__ __launch_bounds__(256) void ln_lrelu_kernel(
    float* __restrict__ X, const float* __restrict__ gm, const float* __restrict__ bt,
    const int* __restrict__ lens, int domask)
{
    const int row = blockIdx.x;
    const int tid = threadIdx.x;
    float4* Xr = (float4*)(X + (size_t)row * NH);
    float4 v = Xr[tid];
    __shared__ float rs[256], rq[256];
    rs[tid] = v.x + v.y + v.z + v.w;
    rq[tid] = v.x * v.x + v.y * v.y + v.z * v.z + v.w * v.w;
    __syncthreads();
    for (int o = 128; o; o >>= 1) {
        if (tid < o) { rs[tid] += rs[tid + o]; rq[tid] += rq[tid + o]; }
        __syncthreads();
    }
    const float mean = rs[0] * (1.f / NH);
    const float var  = rq[0] * (1.f / NH) - mean * mean;
    const float rstd = rsqrtf(var + 1e-5f);
    float mul = 1.f;
    if (domask) {
        const int b = row >> 9, t = row & 511;
        if (t >= lens[b]) mul = 0.f;
    }
    const int gb = tid * 4;
    float y0 = (v.x - mean) * rstd * gm[gb + 0] + bt[gb + 0];
    float y1 = (v.y - mean) * rstd * gm[gb + 1] + bt[gb + 1];
    float y2 = (v.z - mean) * rstd * gm[gb + 2] + bt[gb + 2];
    float y3 = (v.w - mean) * rstd * gm[gb + 3] + bt[gb + 3];
    y0 = (y0 >= 0.f ? y0 : 0.01f * y0) * mul;
    y1 = (y1 >= 0.f ? y1 : 0.01f * y1) * mul;
    y2 = (y2 >= 0.f ? y2 : 0.01f * y2) * mul;
    y3 = (y3 >= 0.f ? y3 : 0.01f * y3) * mul;
    Xr[tid] = make_float4(y0, y1, y2, y3);
}

// ---------------- persistent tensor-core bidirectional LSTM layer ----------------
// 64 blocks: d = blk>>5, block owns 16 hidden units j0..j0+15 (x4 gates = 64 N-cols).
// col c = jl*4 + type; warp w owns cols [8w, 8w+8).
// whh fragments live in 128 registers per thread for the whole sequence.
#define HPAD 516
#define GPAD 68
__global__ __launch_bounds__(256, 1) void lstm_tc_kernel(
    const float* __restrict__ xp,    // [2][MT][G4]
    const float* __restrict__ whh,   // [2][G4][NC] for this layer
    float* __restrict__ out)         // [(b*T+t)][2*NC]
{
    extern __shared__ float sm[];
    float* Hs = sm;                  // 32 x HPAD  (tf32-converted h, A operand)
    float* Gs = sm + 32 * HPAD;      // 32 x GPAD  (mma gate partial results)

    const int tid  = threadIdx.x;
    const int warp = tid >> 5, lane = tid & 31;
    const int qr = lane >> 2, qk = lane & 3;
    const int d    = blockIdx.x >> 5;
    const int j0   = (blockIdx.x & 31) * 16;

    // ---- load whh B-fragments into registers (resident all 512 steps) ----
    const int ncol = 8 * warp + qr;            // 0..63
    const int jl_w = ncol >> 2, ty_w = ncol & 3;
    const int grow = ty_w * NC + j0 + jl_w;
    const float* wrow = whh + (size_t)d * G4 * NC + (size_t)grow * NC;
    uint32_t b0r[64], b1r[64];
#pragma unroll
    for (int kt = 0; kt < 64; kt++) {
        b0r[kt] = tf32rn(__ldg(wrow + kt * 8 + qk));
        b1r[kt] = tf32rn(__ldg(wrow + kt * 8 + qk + 4));
    }

    const float* xpd = xp + (size_t)d * MT * G4;
    float cst[2] = {0.f, 0.f};       // c-state for (b,j) pairs tid and tid+256
    unsigned gen = 0;

    for (int t = 0; t < Tt; t++) {
        const int tt = d ? (Tt - 1 - t) : t;

        if (t > 0) {
            // stage h_{t-1} (dir d, parity t&1) into smem, converting to tf32
            const float4* src4 = (const float4*)g_hbuf[d * 2 + (t & 1)];
#pragma unroll
            for (int r = 0; r < 16; r++) {
                const int idx = r * 256 + tid;       // 4096 float4s
                float4 v = __ldcg(src4 + idx);
                float4 w;
                w.x = __uint_as_float(tf32rn(v.x));
                w.y = __uint_as_float(tf32rn(v.y));
                w.z = __uint_as_float(tf32rn(v.z));
                w.w = __uint_as_float(tf32rn(v.w));
                ((float4*)(Hs + (idx >> 7) * HPAD))[idx & 127] = w;
            }
            __syncthreads();

            float acc[2][4];
#pragma unroll
            for (int mt = 0; mt < 2; mt++)
#pragma unroll
                for (int l = 0; l < 4; l++) acc[mt][l] = 0.f;

#pragma unroll
            for (int kt = 0; kt < 64; kt++) {
                uint32_t b[2] = { b0r[kt], b1r[kt] };
#pragma unroll
                for (int mt = 0; mt < 2; mt++) {
                    const float* hp = Hs + (16 * mt + qr) * HPAD + kt * 8 + qk;
                    uint32_t a[4];
                    a[0] = __float_as_uint(hp[0]);
                    a[1] = __float_as_uint(hp[8 * HPAD]);
                    a[2] = __float_as_uint(hp[4]);
                    a[3] = __float_as_uint(hp[8 * HPAD + 4]);
                    mma_tf32(acc[mt], a, b);
                }
            }
            // write gate partials: c0,c1 -> (row, 2qk), c2,c3 -> (row+8, 2qk)
#pragma unroll
            for (int mt = 0; mt < 2; mt++) {
                *(float2*)&Gs[(16 * mt + qr) * GPAD + 8 * warp + 2 * qk] =
                    make_float2(acc[mt][0], acc[mt][1]);
                *(float2*)&Gs[(16 * mt + qr + 8) * GPAD + 8 * warp + 2 * qk] =
                    make_float2(acc[mt][2], acc[mt][3]);
            }
            __syncthreads();
        }

        // ---- activation: thread handles (b,j) pairs tid and tid+256 ----
#pragma unroll
        for (int pp = 0; pp < 2; pp++) {
            const int p2 = tid + pp * 256;
            const int b = p2 >> 4, jl = p2 & 15, j = j0 + jl;
            const float* xpr = xpd + ((size_t)b * Tt + tt) * G4;
            float gi = __ldg(xpr + j);
            float gf = __ldg(xpr + NC + j);
            float gg = __ldg(xpr + 2 * NC + j);
            float go = __ldg(xpr + 3 * NC + j);
            if (t > 0) {
                float4 gv = *(const float4*)&Gs[b * GPAD + 4 * jl];
                gi += gv.x; gf += gv.y; gg += gv.z; go += gv.w;
            }
            const float si = 1.f / (1.f + expf(-gi));
            const float sf = 1.f / (1.f + expf(-gf));
            const float sg = tanhf(gg);
            const float so = 1.f / (1.f + expf(-go));
            cst[pp] = sf * cst[pp] + si * sg;
            const float h = so * tanhf(cst[pp]);
            __stcg(&g_hbuf[d * 2 + ((t + 1) & 1)][b * NC + j], h);
            out[((size_t)b * Tt + tt) * (2 * NC) + d * NC + j] = h;
        }

        gridbar(gridDim.x, gen);
    }
}

// ---------------- attention scores ----------------
__global__ __launch_bounds__(256) void scores_kernel(
    const float* __restrict__ h, const float* __restrict__ wu,
    const float* __restrict__ bu, const int* __restrict__ lens,
    float* __restrict__ sc)
{
    const int gid = blockIdx.x * 256 + threadIdx.x;
    const int w = gid >> 5, lane = gid & 31;
    const float* hr = h + (size_t)w * (2 * NC);
    float s = 0.f;
    for (int i = lane; i < 2 * NC; i += 32) s = fmaf(hr[i], wu[i], s);
#pragma unroll
    for (int o = 16; o; o >>= 1) s += __shfl_xor_sync(0xffffffffu, s, o);
    if (lane == 0) {
        const int b = w >> 9, t = w & 511;
        sc[w] = (t < lens[b]) ? (s + bu[0]) : -INFINITY;
    }
}

// ---------------- masked softmax + weighted pool ----------------
__global__ __launch_bounds__(256) void softpool_kernel(
    const float* __restrict__ h, const float* __restrict__ sc,
    float* __restrict__ pooled)
{
    const int b = blockIdx.x, tid = threadIdx.x;
    __shared__ float al[512];
    __shared__ float red[256];
    float m = -INFINITY;
    for (int t = tid; t < 512; t += 256) m = fmaxf(m, sc[b * 512 + t]);
    red[tid] = m; __syncthreads();
    for (int o = 128; o; o >>= 1) {
        if (tid < o) red[tid] = fmaxf(red[tid], red[tid + o]);
        __syncthreads();
    }
    m = red[0]; __syncthreads();
    float s = 0.f;
    for (int t = tid; t < 512; t += 256) {
        const float e = expf(sc[b * 512 + t] - m);
        al[t] = e; s += e;
    }
    red[tid] = s; __syncthreads();
    for (int o = 128; o; o >>= 1) {
        if (tid < o) red[tid] += red[tid + o];
        __syncthreads();
    }
    const float inv = 1.f / red[0];
    __syncthreads();
    for (int d2 = tid; d2 < 2 * NC; d2 += 256) {
        float acc = 0.f;
        for (int t = 0; t < 512; t++)
            acc = fmaf(al[t], h[((size_t)b * 512 + t) * (2 * NC) + d2], acc);
        pooled[b * (2 * NC) + d2] = acc * inv;
    }
}

// ---------------- final classifier ----------------
__global__ __launch_bounds__(256) void final_kernel(
    const float* __restrict__ pooled, const float* __restrict__ Wc,
    const float* __restrict__ bc, float* __restrict__ out)
{
    const int tid = threadIdx.x;
    const int b = tid >> 3, o = tid & 7;
    const float* p = pooled + b * (2 * NC);
    const float* w = Wc + o * (2 * NC);
    float acc = bc[o];
    for (int k = 0; k < 2 * NC; k++) acc = fmaf(p[k], w[k], acc);
    out[b * NOUT + o] = acc;
}

// ---------------- launch ----------------
extern "C" void kernel_launch(void* const* d_in, const int* in_sizes, int n_in,
                              void* d_out, int out_size)
{
    const float* x    = (const float*)d_in[0];
    const int*   lens = (const int*)  d_in[1];
    const float* W1   = (const float*)d_in[2];
    const float* b1   = (const float*)d_in[3];
    const float* g1   = (const float*)d_in[4];
    const float* be1  = (const float*)d_in[5];
    const float* W2   = (const float*)d_in[6];
    const float* b2   = (const float*)d_in[7];
    const float* g2   = (const float*)d_in[8];
    const float* be2  = (const float*)d_in[9];
    const float* wih  = (const float*)d_in[10];
    const float* whh  = (const float*)d_in[11];
    const float* bih  = (const float*)d_in[12];
    const float* bhh  = (const float*)d_in[13];
    const float* wu   = (const float*)d_in[14];
    const float* bu   = (const float*)d_in[15];
    const float* Wc   = (const float*)d_in[16];
    const float* bc   = (const float*)d_in[17];
    float* out = (float*)d_out;

    float *h1, *h2, *xpb, *l0, *l1, *sc, *pooled;
    cudaGetSymbolAddress((void**)&h1, g_h1);
    cudaGetSymbolAddress((void**)&h2, g_h2);
    cudaGetSymbolAddress((void**)&xpb, g_xp);
    cudaGetSymbolAddress((void**)&l0, g_l0);
    cudaGetSymbolAddress((void**)&l1, g_l1);
    cudaGetSymbolAddress((void**)&sc, g_sc);
    cudaGetSymbolAddress((void**)&pooled, g_pooled);

    const int lstm_smem = (32 * HPAD + 32 * GPAD) * 4;
    cudaFuncSetAttribute(lstm_tc_kernel,
                         cudaFuncAttributeMaxDynamicSharedMemorySize, lstm_smem);

    // MLP
    gemm_tf32_kernel<<<dim3(NH / 128, MT / 128), 256>>>(x, W1, b1, nullptr, h1, MT, NH, FDim);
    ln_lrelu_kernel<<<MT, 256>>>(h1, g1, be1, nullptr, 0);
    gemm_tf32_kernel<<<dim3(NH / 128, MT / 128), 256>>>(h1, W2, b2, nullptr, h2, MT, NH, NH);
    ln_lrelu_kernel<<<MT, 256>>>(h2, g2, be2, lens, 1);

    // 2 bidirectional LSTM layers
    const float* lin = h2;
    float* louts[2] = { l0, l1 };
    for (int l = 0; l < 2; l++) {
        for (int dd = 0; dd < 2; dd++) {
            gemm_tf32_kernel<<<dim3(G4 / 128, MT / 128), 256>>>(
                lin, wih + (size_t)(l * 2 + dd) * G4 * NH,
                bih + (size_t)(l * 2 + dd) * G4, bhh + (size_t)(l * 2 + dd) * G4,
                xpb + (size_t)dd * MT * G4, MT, G4, NH);
        }
        reset_bar_kernel<<<1, 1>>>();
        lstm_tc_kernel<<<64, 256, lstm_smem>>>(xpb, whh + (size_t)l * 2 * G4 * NC, louts[l]);
        lin = louts[l];
    }

    // attention + head
    scores_kernel<<<MT / 8, 256>>>(l1, wu, bu, lens, sc);
    softpool_kernel<<<Bq, 256>>>(l1, sc, pooled);
    final_kernel<<<1, 256>>>(pooled, Wc, bc, out);
}

// round 7
// speedup vs baseline: 2.3944x; 1.0031x over previous
#include <cuda_runtime.h>
#include <math.h>
#include <stdint.h>

#define Bq   32
#define Tt   512
#define FDim 256
#define NH   1024
#define NC   512
#define G4   2048      // 4*NC
#define G8   4096      // 2 dirs * 4*NC
#define NOUT 8
#define MT   (Bq*Tt)   // 16384 rows

// ---------------- device scratch ----------------
__device__ float g_h1[(size_t)MT*NH];
__device__ float g_h2[(size_t)MT*NH];
__device__ float g_xp[(size_t)MT*G8];          // [(b*T+t)][dir*G4 + g]
__device__ float g_l0[(size_t)MT*2*NC];
__device__ float g_l1[(size_t)MT*2*NC];
__device__ float g_hbuf[4][Bq*NC];             // [dir*2+parity][b][j]
__device__ float g_sc[Bq*Tt];
__device__ float g_pooled[Bq*2*NC];
__device__ float g_xc[(size_t)MT*FDim];        // tf32-rounded x
__device__ float g_w1c[(size_t)NH*FDim];
__device__ float g_w2c[(size_t)NH*NH];
__device__ float g_wihc[(size_t)2*G8*NH];      // tf32-rounded wih, both layers
__device__ unsigned g_bar_arrive;
__device__ volatile unsigned g_bar_gen;

// ---------------- grid barrier ----------------
__device__ __forceinline__ void gridbar(unsigned nb, unsigned &gen) {
    __syncthreads();
    if (threadIdx.x == 0) {
        __threadfence();
        gen++;
        unsigned prev = atomicAdd(&g_bar_arrive, 1u);
        if (prev == nb * gen - 1u) {
            __threadfence();
            g_bar_gen = gen;
        } else {
            while (g_bar_gen < gen) { __nanosleep(32); }
        }
    }
    __syncthreads();
}

__global__ void reset_bar_kernel() {
    g_bar_arrive = 0u;
    g_bar_gen = 0u;
}

// ---------------- tf32 helpers ----------------
__device__ __forceinline__ unsigned su32(const void* p) {
    unsigned r;
    asm("{.reg .u64 t; cvta.to.shared.u64 t, %1; cvt.u32.u64 %0, t;}" : "=r"(r) : "l"(p));
    return r;
}
__device__ __forceinline__ void cp16(unsigned s, const void* g) {
    asm volatile("cp.async.cg.shared.global [%0], [%1], 16;\n" :: "r"(s), "l"(g));
}
__device__ __forceinline__ uint32_t tf32rn(float x) {
    uint32_t r;
    asm("cvt.rna.tf32.f32 %0, %1;\n" : "=r"(r) : "f"(x));
    return r;
}
__device__ __forceinline__ float tf32f(float x) {
    return __uint_as_float(tf32rn(x));
}
__device__ __forceinline__ void mma_tf32(float (&c)[4], const uint32_t (&a)[4], const uint32_t (&b)[2]) {
    asm volatile("mma.sync.aligned.m16n8k8.row.col.f32.tf32.tf32.f32 "
        "{%0,%1,%2,%3}, {%4,%5,%6,%7}, {%8,%9}, {%0,%1,%2,%3};\n"
        : "+f"(c[0]), "+f"(c[1]), "+f"(c[2]), "+f"(c[3])
        : "r"(a[0]), "r"(a[1]), "r"(a[2]), "r"(a[3]), "r"(b[0]), "r"(b[1]));
}

// ---------------- elementwise tf32 round ----------------
__global__ __launch_bounds__(256) void cvt_tf32_kernel(
    const float4* __restrict__ src, float4* __restrict__ dst, int n4)
{
    const int i = blockIdx.x * 256 + threadIdx.x;
    if (i < n4) {
        float4 v = src[i];
        v.x = tf32f(v.x); v.y = tf32f(v.y); v.z = tf32f(v.z); v.w = tf32f(v.w);
        dst[i] = v;
    }
}

// ---------------- tf32 GEMM (operands pre-rounded): C = A[M,K]*W[N,K]^T + b1 (+b2) ----------------
#define PADK 20
__global__ __launch_bounds__(256) void gemm_tf32_kernel(
    const float* __restrict__ A, const float* __restrict__ W,
    const float* __restrict__ bias1, const float* __restrict__ bias2,
    float* __restrict__ C, int M, int N, int K)
{
    __shared__ float As[2][128 * PADK];
    __shared__ float Ws[2][128 * PADK];
    const int tid  = threadIdx.x;
    const int warp = tid >> 5, lane = tid & 31;
    const int wm = warp & 3, wn = warp >> 2;
    const int qr = lane >> 2, qk = lane & 3;
    const int m0 = blockIdx.y * 128;
    const int n0 = blockIdx.x * 128;

    const int ca = tid * 2, cb = ca + 1;
    const int ra = ca >> 2, ka = (ca & 3) * 4;
    const int rb = cb >> 2, kb = (cb & 3) * 4;

    const float* Ag = A + (size_t)m0 * K;
    const float* Wg = W + (size_t)n0 * K;

    const unsigned sAa = su32(&As[0][ra * PADK + ka]);
    const unsigned sAb = su32(&As[0][rb * PADK + kb]);
    const unsigned sWa = su32(&Ws[0][ra * PADK + ka]);
    const unsigned sWb = su32(&Ws[0][rb * PADK + kb]);
    const unsigned stgB = 128 * PADK * 4;

    float acc[2][8][4];
#pragma unroll
    for (int i = 0; i < 2; i++)
#pragma unroll
        for (int j = 0; j < 8; j++)
#pragma unroll
            for (int l = 0; l < 4; l++) acc[i][j][l] = 0.f;

    const int nk = K >> 4;

    cp16(sAa, Ag + (size_t)ra * K + ka);
    cp16(sAb, Ag + (size_t)rb * K + kb);
    cp16(sWa, Wg + (size_t)ra * K + ka);
    cp16(sWb, Wg + (size_t)rb * K + kb);
    asm volatile("cp.async.commit_group;\n");

    for (int kt = 0; kt < nk; kt++) {
        if (kt + 1 < nk) {
            const int k0 = (kt + 1) * 16;
            const unsigned so = ((kt + 1) & 1) * stgB;
            cp16(sAa + so, Ag + (size_t)ra * K + k0 + ka);
            cp16(sAb + so, Ag + (size_t)rb * K + k0 + kb);
            cp16(sWa + so, Wg + (size_t)ra * K + k0 + ka);
            cp16(sWb + so, Wg + (size_t)rb * K + k0 + kb);
            asm volatile("cp.async.commit_group;\n");
            asm volatile("cp.async.wait_group 1;\n");
        } else {
            asm volatile("cp.async.wait_group 0;\n");
        }
        __syncthreads();

        const uint32_t* Ab_ = (const uint32_t*)&As[kt & 1][0];
        const uint32_t* Bb_ = (const uint32_t*)&Ws[kt & 1][0];
#pragma unroll
        for (int ks = 0; ks < 16; ks += 8) {
            uint32_t a[2][4];
#pragma unroll
            for (int mt = 0; mt < 2; mt++) {
                const uint32_t* ap = Ab_ + (wm * 32 + mt * 16 + qr) * PADK + ks + qk;
                a[mt][0] = ap[0];
                a[mt][1] = ap[8 * PADK];
                a[mt][2] = ap[4];
                a[mt][3] = ap[8 * PADK + 4];
            }
#pragma unroll
            for (int nt = 0; nt < 8; nt++) {
                const uint32_t* bp = Bb_ + (wn * 64 + nt * 8 + qr) * PADK + ks + qk;
                uint32_t b[2];
                b[0] = bp[0];
                b[1] = bp[4];
                mma_tf32(acc[0][nt], a[0], b);
                mma_tf32(acc[1][nt], a[1], b);
            }
        }
        __syncthreads();
    }

#pragma unroll
    for (int mt = 0; mt < 2; mt++) {
        const int mr = m0 + wm * 32 + mt * 16 + qr;
#pragma unroll
        for (int nt = 0; nt < 8; nt++) {
            const int n = n0 + wn * 64 + nt * 8 + qk * 2;
            float b0 = bias1[n], b1 = bias1[n + 1];
            if (bias2) { b0 += bias2[n]; b1 += bias2[n + 1]; }
            *(float2*)&C[(size_t)mr * N + n]       = make_float2(acc[mt][nt][0] + b0, acc[mt][nt][1] + b1);
            *(float2*)&C[(size_t)(mr + 8) * N + n] = make_float2(acc[mt][nt][2] + b0, acc[mt][nt][3] + b1);
        }
    }
}

// ---------------- LayerNorm + LeakyReLU (+ mask), writes tf32-rounded ----------------
__global__ __launch_bounds__(256) void ln_lrelu_kernel(
    float* __restrict__ X, const float* __restrict__ gm, const float* __restrict__ bt,
    const int* __restrict__ lens, int domask)
{
    const int row = blockIdx.x;
    const int tid = threadIdx.x;
    float4* Xr = (float4*)(X + (size_t)row * NH);
    float4 v = Xr[tid];
    __shared__ float rs[256], rq[256];
    rs[tid] = v.x + v.y + v.z + v.w;
    rq[tid] = v.x * v.x + v.y * v.y + v.z * v.z + v.w * v.w;
    __syncthreads();
    for (int o = 128; o; o >>= 1) {
        if (tid < o) { rs[tid] += rs[tid + o]; rq[tid] += rq[tid + o]; }
        __syncthreads();
    }
    const float mean = rs[0] * (1.f / NH);
    const float var  = rq[0] * (1.f / NH) - mean * mean;
    const float rstd = rsqrtf(var + 1e-5f);
    float mul = 1.f;
    if (domask) {
        const int b = row >> 9, t = row & 511;
        if (t >= lens[b]) mul = 0.f;
    }
    const int gb = tid * 4;
    float y0 = (v.x - mean) * rstd * gm[gb + 0] + bt[gb + 0];
    float y1 = (v.y - mean) * rstd * gm[gb + 1] + bt[gb + 1];
    float y2 = (v.z - mean) * rstd * gm[gb + 2] + bt[gb + 2];
    float y3 = (v.w - mean) * rstd * gm[gb + 3] + bt[gb + 3];
    y0 = tf32f((y0 >= 0.f ? y0 : 0.01f * y0) * mul);
    y1 = tf32f((y1 >= 0.f ? y1 : 0.01f * y1) * mul);
    y2 = tf32f((y2 >= 0.f ? y2 : 0.01f * y2) * mul);
    y3 = tf32f((y3 >= 0.f ? y3 : 0.01f * y3) * mul);
    Xr[tid] = make_float4(y0, y1, y2, y3);
}

// ---------------- persistent tensor-core bidirectional LSTM layer ----------------
// 64 blocks: d = blk>>5, block owns 16 hidden units (x4 gates = 64 N-cols).
#define HPAD 516
#define GPAD 68
__global__ __launch_bounds__(256, 1) void lstm_tc_kernel(
    const float* __restrict__ xp,    // [MT][G8], dir at col offset d*G4
    const float* __restrict__ whh,   // [2][G4][NC] for this layer
    float* __restrict__ out)         // [(b*T+t)][2*NC]
{
    extern __shared__ float sm[];
    float* Hs = sm;                  // 32 x HPAD
    float* Gs = sm + 32 * HPAD;      // 32 x GPAD

    const int tid  = threadIdx.x;
    const int warp = tid >> 5, lane = tid & 31;
    const int qr = lane >> 2, qk = lane & 3;
    const int d    = blockIdx.x >> 5;
    const int j0   = (blockIdx.x & 31) * 16;

    const int ncol = 8 * warp + qr;
    const int jl_w = ncol >> 2, ty_w = ncol & 3;
    const int grow = ty_w * NC + j0 + jl_w;
    const float* wrow = whh + (size_t)d * G4 * NC + (size_t)grow * NC;
    uint32_t b0r[64], b1r[64];
#pragma unroll
    for (int kt = 0; kt < 64; kt++) {
        b0r[kt] = tf32rn(__ldg(wrow + kt * 8 + qk));
        b1r[kt] = tf32rn(__ldg(wrow + kt * 8 + qk + 4));
    }

    const float* xpd = xp + (size_t)d * G4;
    float cst[2] = {0.f, 0.f};
    unsigned gen = 0;

    for (int t = 0; t < Tt; t++) {
        const int tt = d ? (Tt - 1 - t) : t;

        if (t > 0) {
            const float4* src4 = (const float4*)g_hbuf[d * 2 + (t & 1)];
#pragma unroll
            for (int r = 0; r < 16; r++) {
                const int idx = r * 256 + tid;
                float4 v = __ldcg(src4 + idx);
                float4 w;
                w.x = tf32f(v.x); w.y = tf32f(v.y);
                w.z = tf32f(v.z); w.w = tf32f(v.w);
                ((float4*)(Hs + (idx >> 7) * HPAD))[idx & 127] = w;
            }
            __syncthreads();

            float acc[2][4];
#pragma unroll
            for (int mt = 0; mt < 2; mt++)
#pragma unroll
                for (int l = 0; l < 4; l++) acc[mt][l] = 0.f;

#pragma unroll
            for (int kt = 0; kt < 64; kt++) {
                uint32_t b[2] = { b0r[kt], b1r[kt] };
#pragma unroll
                for (int mt = 0; mt < 2; mt++) {
                    const float* hp = Hs + (16 * mt + qr) * HPAD + kt * 8 + qk;
                    uint32_t a[4];
                    a[0] = __float_as_uint(hp[0]);
                    a[1] = __float_as_uint(hp[8 * HPAD]);
                    a[2] = __float_as_uint(hp[4]);
                    a[3] = __float_as_uint(hp[8 * HPAD + 4]);
                    mma_tf32(acc[mt], a, b);
                }
            }
#pragma unroll
            for (int mt = 0; mt < 2; mt++) {
                *(float2*)&Gs[(16 * mt + qr) * GPAD + 8 * warp + 2 * qk] =
                    make_float2(acc[mt][0], acc[mt][1]);
                *(float2*)&Gs[(16 * mt + qr + 8) * GPAD + 8 * warp + 2 * qk] =
                    make_float2(acc[mt][2], acc[mt][3]);
            }
            __syncthreads();
        }

#pragma unroll
        for (int pp = 0; pp < 2; pp++) {
            const int p2 = tid + pp * 256;
            const int b = p2 >> 4, jl = p2 & 15, j = j0 + jl;
            const float* xpr = xpd + ((size_t)b * Tt + tt) * G8;
            float gi = __ldg(xpr + j);
            float gf = __ldg(xpr + NC + j);
            float gg = __ldg(xpr + 2 * NC + j);
            float go = __ldg(xpr + 3 * NC + j);
            if (t > 0) {
                float4 gv = *(const float4*)&Gs[b * GPAD + 4 * jl];
                gi += gv.x; gf += gv.y; gg += gv.z; go += gv.w;
            }
            const float si = 1.f / (1.f + expf(-gi));
            const float sf = 1.f / (1.f + expf(-gf));
            const float sg = tanhf(gg);
            const float so = 1.f / (1.f + expf(-go));
            cst[pp] = sf * cst[pp] + si * sg;
            const float h = so * tanhf(cst[pp]);
            __stcg(&g_hbuf[d * 2 + ((t + 1) & 1)][b * NC + j], h);
            out[((size_t)b * Tt + tt) * (2 * NC) + d * NC + j] = tf32f(h);
        }

        gridbar(gridDim.x, gen);
    }
}

// ---------------- attention scores ----------------
__global__ __launch_bounds__(256) void scores_kernel(
    const float* __restrict__ h, const float* __restrict__ wu,
    const float* __restrict__ bu, const int* __restrict__ lens,
    float* __restrict__ sc)
{
    const int gid = blockIdx.x * 256 + threadIdx.x;
    const int w = gid >> 5, lane = gid & 31;
    const float* hr = h + (size_t)w * (2 * NC);
    float s = 0.f;
    for (int i = lane; i < 2 * NC; i += 32) s = fmaf(hr[i], wu[i], s);
#pragma unroll
    for (int o = 16; o; o >>= 1) s += __shfl_xor_sync(0xffffffffu, s, o);
    if (lane == 0) {
        const int b = w >> 9, t = w & 511;
        sc[w] = (t < lens[b]) ? (s + bu[0]) : -INFINITY;
    }
}

// ---------------- masked softmax + weighted pool ----------------
__global__ __launch_bounds__(256) void softpool_kernel(
    const float* __restrict__ h, const float* __restrict__ sc,
    float* __restrict__ pooled)
{
    const int b = blockIdx.x, tid = threadIdx.x;
    __shared__ float al[512];
    __shared__ float red[256];
    float m = -INFINITY;
    for (int t = tid; t < 512; t += 256) m = fmaxf(m, sc[b * 512 + t]);
    red[tid] = m; __syncthreads();
    for (int o = 128; o; o >>= 1) {
        if (tid < o) red[tid] = fmaxf(red[tid], red[tid + o]);
        __syncthreads();
    }
    m = red[0]; __syncthreads();
    float s = 0.f;
    for (int t = tid; t < 512; t += 256) {
        const float e = expf(sc[b * 512 + t] - m);
        al[t] = e; s += e;
    }
    red[tid] = s; __syncthreads();
    for (int o = 128; o; o >>= 1) {
        if (tid < o) red[tid] += red[tid + o];
        __syncthreads();
    }
    const float inv = 1.f / red[0];
    __syncthreads();
    for (int d2 = tid; d2 < 2 * NC; d2 += 256) {
        float acc = 0.f;
        for (int t = 0; t < 512; t++)
            acc = fmaf(al[t], h[((size_t)b * 512 + t) * (2 * NC) + d2], acc);
        pooled[b * (2 * NC) + d2] = acc * inv;
    }
}

// ---------------- final classifier ----------------
__global__ __launch_bounds__(256) void final_kernel(
    const float* __restrict__ pooled, const float* __restrict__ Wc,
    const float* __restrict__ bc, float* __restrict__ out)
{
    const int tid = threadIdx.x;
    const int b = tid >> 3, o = tid & 7;
    const float* p = pooled + b * (2 * NC);
    const float* w = Wc + o * (2 * NC);
    float acc = bc[o];
    for (int k = 0; k < 2 * NC; k++) acc = fmaf(p[k], w[k], acc);
    out[b * NOUT + o] = acc;
}

// ---------------- launch ----------------
extern "C" void kernel_launch(void* const* d_in, const int* in_sizes, int n_in,
                              void* d_out, int out_size)
{
    const float* x    = (const float*)d_in[0];
    const int*   lens = (const int*)  d_in[1];
    const float* W1   = (const float*)d_in[2];
    const float* b1   = (const float*)d_in[3];
    const float* g1   = (const float*)d_in[4];
    const float* be1  = (const float*)d_in[5];
    const float* W2   = (const float*)d_in[6];
    const float* b2   = (const float*)d_in[7];
    const float* g2   = (const float*)d_in[8];
    const float* be2  = (const float*)d_in[9];
    const float* wih  = (const float*)d_in[10];
    const float* whh  = (const float*)d_in[11];
    const float* bih  = (const float*)d_in[12];
    const float* bhh  = (const float*)d_in[13];
    const float* wu   = (const float*)d_in[14];
    const float* bu   = (const float*)d_in[15];
    const float* Wc   = (const float*)d_in[16];
    const float* bc   = (const float*)d_in[17];
    float* out = (float*)d_out;

    float *h1, *h2, *xpb, *l0, *l1, *sc, *pooled, *xc, *w1c, *w2c, *wihc;
    cudaGetSymbolAddress((void**)&h1, g_h1);
    cudaGetSymbolAddress((void**)&h2, g_h2);
    cudaGetSymbolAddress((void**)&xpb, g_xp);
    cudaGetSymbolAddress((void**)&l0, g_l0);
    cudaGetSymbolAddress((void**)&l1, g_l1);
    cudaGetSymbolAddress((void**)&sc, g_sc);
    cudaGetSymbolAddress((void**)&pooled, g_pooled);
    cudaGetSymbolAddress((void**)&xc, g_xc);
    cudaGetSymbolAddress((void**)&w1c, g_w1c);
    cudaGetSymbolAddress((void**)&w2c, g_w2c);
    cudaGetSymbolAddress((void**)&wihc, g_wihc);

    const int lstm_smem = (32 * HPAD + 32 * GPAD) * 4;
    cudaFuncSetAttribute(lstm_tc_kernel,
                         cudaFuncAttributeMaxDynamicSharedMemorySize, lstm_smem);

    // pre-convert operands to tf32 (rna) once
    cvt_tf32_kernel<<<(MT * FDim / 4 + 255) / 256, 256>>>((const float4*)x, (float4*)xc, MT * FDim / 4);
    cvt_tf32_kernel<<<(NH * FDim / 4 + 255) / 256, 256>>>((const float4*)W1, (float4*)w1c, NH * FDim / 4);
    cvt_tf32_kernel<<<(NH * NH / 4 + 255) / 256, 256>>>((const float4*)W2, (float4*)w2c, NH * NH / 4);
    cvt_tf32_kernel<<<(2 * G8 * NH / 4 + 255) / 256, 256>>>((const float4*)wih, (float4*)wihc, 2 * G8 * NH / 4);

    // MLP
    gemm_tf32_kernel<<<dim3(NH / 128, MT / 128), 256>>>(xc, w1c, b1, nullptr, h1, MT, NH, FDim);
    ln_lrelu_kernel<<<MT, 256>>>(h1, g1, be1, nullptr, 0);
    gemm_tf32_kernel<<<dim3(NH / 128, MT / 128), 256>>>(h1, w2c, b2, nullptr, h2, MT, NH, NH);
    ln_lrelu_kernel<<<MT, 256>>>(h2, g2, be2, lens, 1);

    // 2 bidirectional LSTM layers (merged-dir xp GEMM: N = 4096)
    const float* lin = h2;
    float* louts[2] = { l0, l1 };
    for (int l = 0; l < 2; l++) {
        gemm_tf32_kernel<<<dim3(G8 / 128, MT / 128), 256>>>(
            lin, wihc + (size_t)l * G8 * NH,
            bih + (size_t)l * G8, bhh + (size_t)l * G8,
            xpb, MT, G8, NH);
        reset_bar_kernel<<<1, 1>>>();
        lstm_tc_kernel<<<64, 256, lstm_smem>>>(xpb, whh + (size_t)l * 2 * G4 * NC, louts[l]);
        lin = louts[l];
    }

    // attention + head
    scores_kernel<<<MT / 8, 256>>>(l1, wu, bu, lens, sc);
    softpool_kernel<<<Bq, 256>>>(l1, sc, pooled);
    final_kernel<<<1, 256>>>(pooled, Wc, bc, out);
}

// round 11
// speedup vs baseline: 2.7509x; 1.1489x over previous
#include <cuda_runtime.h>
#include <cuda_fp16.h>
#include <math.h>
#include <stdint.h>
#include <string.h>

#define Bq   32
#define Tt   512
#define FDim 256
#define NH   1024
#define NC   512
#define G4   2048      // 4*NC
#define G8   4096      // 2 dirs * 4*NC
#define NOUT 8
#define MT   (Bq*Tt)   // 16384 rows

// ---------------- device scratch ----------------
__device__ float  g_h1[(size_t)MT*NH];
__device__ float  g_h2[(size_t)MT*NH];
__device__ float  g_xp[(size_t)MT*G8];         // [(b*T+t)][dir*G4 + g]
__device__ float  g_l0[(size_t)MT*2*NC];
__device__ float  g_l1[(size_t)MT*2*NC];
__device__ float  g_hbuf[4][Bq*NC];            // [dir*2+parity][b][j]
__device__ float  g_sc[Bq*Tt];
__device__ float  g_pooled[Bq*2*NC];
__device__ __half g_xh[(size_t)MT*FDim];
__device__ __half g_h1h[(size_t)MT*NH];
__device__ __half g_h2h[(size_t)MT*NH];
__device__ __half g_l0h[(size_t)MT*2*NC];
__device__ __half g_w1h[(size_t)NH*FDim];
__device__ __half g_w2h[(size_t)NH*NH];
__device__ __half g_wihh[(size_t)2*G8*NH];
__device__ unsigned g_bar_arrive;
__device__ volatile unsigned g_bar_gen;

// ---------------- grid barrier ----------------
__device__ __forceinline__ void gridbar(unsigned nb, unsigned &gen) {
    __syncthreads();
    if (threadIdx.x == 0) {
        __threadfence();
        gen++;
        unsigned prev = atomicAdd(&g_bar_arrive, 1u);
        if (prev == nb * gen - 1u) {
            __threadfence();
            g_bar_gen = gen;
        } else {
            while (g_bar_gen < gen) { __nanosleep(32); }
        }
    }
    __syncthreads();
}

__global__ void reset_bar_kernel() {
    g_bar_arrive = 0u;
    g_bar_gen = 0u;
}

// ---------------- helpers ----------------
__device__ __forceinline__ unsigned su32(const void* p) {
    unsigned r;
    asm("{.reg .u64 t; cvta.to.shared.u64 t, %1; cvt.u32.u64 %0, t;}" : "=r"(r) : "l"(p));
    return r;
}
__device__ __forceinline__ void cp16(unsigned s, const void* g) {
    asm volatile("cp.async.cg.shared.global [%0], [%1], 16;\n" :: "r"(s), "l"(g));
}
__device__ __forceinline__ uint32_t h2_as_u32(__half2 h) {
    __half2_raw r = *(__half2_raw*)&h;
    return (uint32_t)r.x | ((uint32_t)r.y << 16);
}
__device__ __forceinline__ uint32_t tf32rn(float x) {
    uint32_t r;
    asm("cvt.rna.tf32.f32 %0, %1;\n" : "=r"(r) : "f"(x));
    return r;
}
__device__ __forceinline__ float tf32f(float x) {
    return __uint_as_float(tf32rn(x));
}
__device__ __forceinline__ void mma_tf32(float (&c)[4], const uint32_t (&a)[4], const uint32_t (&b)[2]) {
    asm volatile("mma.sync.aligned.m16n8k8.row.col.f32.tf32.tf32.f32 "
        "{%0,%1,%2,%3}, {%4,%5,%6,%7}, {%8,%9}, {%0,%1,%2,%3};\n"
        : "+f"(c[0]), "+f"(c[1]), "+f"(c[2]), "+f"(c[3])
        : "r"(a[0]), "r"(a[1]), "r"(a[2]), "r"(a[3]), "r"(b[0]), "r"(b[1]));
}
__device__ __forceinline__ void mma_f16(float (&c)[4], const uint32_t (&a)[4], const uint32_t (&b)[2]) {
    asm volatile("mma.sync.aligned.m16n8k16.row.col.f32.f16.f16.f32 "
        "{%0,%1,%2,%3}, {%4,%5,%6,%7}, {%8,%9}, {%0,%1,%2,%3};\n"
        : "+f"(c[0]), "+f"(c[1]), "+f"(c[2]), "+f"(c[3])
        : "r"(a[0]), "r"(a[1]), "r"(a[2]), "r"(a[3]), "r"(b[0]), "r"(b[1]));
}

// ---------------- elementwise fp32 -> fp16 ----------------
__global__ __launch_bounds__(256) void cvt_f16_kernel(
    const float4* __restrict__ src, uint2* __restrict__ dst, int n4)
{
    const int i = blockIdx.x * 256 + threadIdx.x;
    if (i < n4) {
        float4 v = src[i];
        uint2 o;
        o.x = h2_as_u32(__floats2half2_rn(v.x, v.y));
        o.y = h2_as_u32(__floats2half2_rn(v.z, v.w));
        dst[i] = o;
    }
}

// ---------------- fp16 GEMM: C = A[M,K]*W[N,K]^T + b1 (+b2), fp32 accum/out ----------------
// Block 128x128, BK = 32 halves, double-buffered cp.async.
#define PADH 40   // halves per smem row (80B stride: conflict-free)
__global__ __launch_bounds__(256) void gemm_f16_kernel(
    const __half* __restrict__ A, const __half* __restrict__ W,
    const float* __restrict__ bias1, const float* __restrict__ bias2,
    float* __restrict__ C, int M, int N, int K)
{
    __shared__ __half As[2][128 * PADH];
    __shared__ __half Ws[2][128 * PADH];
    const int tid  = threadIdx.x;
    const int warp = tid >> 5, lane = tid & 31;
    const int wm = warp & 3, wn = warp >> 2;        // 4 x 2 warp grid
    const int qr = lane >> 2, qk = lane & 3;
    const int m0 = blockIdx.y * 128;
    const int n0 = blockIdx.x * 128;

    // staging: per stage A/W each = 128 rows x 4 chunks(16B); thread does 2 A + 2 W chunks
    const int ca = tid * 2, cb = ca + 1;
    const int ra = ca >> 2, ka = (ca & 3) * 8;      // halves
    const int rb = cb >> 2, kb = (cb & 3) * 8;

    const __half* Ag = A + (size_t)m0 * K;
    const __half* Wg = W + (size_t)n0 * K;

    const unsigned sAa = su32(&As[0][ra * PADH + ka]);
    const unsigned sAb = su32(&As[0][rb * PADH + kb]);
    const unsigned sWa = su32(&Ws[0][ra * PADH + ka]);
    const unsigned sWb = su32(&Ws[0][rb * PADH + kb]);
    const unsigned stgB = 128 * PADH * 2;           // stage stride (bytes)

    float acc[2][8][4];
#pragma unroll
    for (int i = 0; i < 2; i++)
#pragma unroll
        for (int j = 0; j < 8; j++)
#pragma unroll
            for (int l = 0; l < 4; l++) acc[i][j][l] = 0.f;

    const int nk = K >> 5;  // BK = 32 halves

    cp16(sAa, Ag + (size_t)ra * K + ka);
    cp16(sAb, Ag + (size_t)rb * K + kb);
    cp16(sWa, Wg + (size_t)ra * K + ka);
    cp16(sWb, Wg + (size_t)rb * K + kb);
    asm volatile("cp.async.commit_group;\n");

    for (int kt = 0; kt < nk; kt++) {
        if (kt + 1 < nk) {
            const int k0 = (kt + 1) * 32;
            const unsigned so = ((kt + 1) & 1) * stgB;
            cp16(sAa + so, Ag + (size_t)ra * K + k0 + ka);
            cp16(sAb + so, Ag + (size_t)rb * K + k0 + kb);
            cp16(sWa + so, Wg + (size_t)ra * K + k0 + ka);
            cp16(sWb + so, Wg + (size_t)rb * K + k0 + kb);
            asm volatile("cp.async.commit_group;\n");
            asm volatile("cp.async.wait_group 1;\n");
        } else {
            asm volatile("cp.async.wait_group 0;\n");
        }
        __syncthreads();

        const uint32_t* Ab_ = (const uint32_t*)&As[kt & 1][0];
        const uint32_t* Bb_ = (const uint32_t*)&Ws[kt & 1][0];
#pragma unroll
        for (int ks = 0; ks < 32; ks += 16) {
            uint32_t a[2][4];
#pragma unroll
            for (int mt = 0; mt < 2; mt++) {
                // u32 view: row stride = PADH/2 = 20 u32
                const uint32_t* ap = Ab_ + (wm * 32 + mt * 16 + qr) * (PADH / 2) + (ks >> 1) + qk;
                a[mt][0] = ap[0];                   // (row,   k+2qk)
                a[mt][1] = ap[8 * (PADH / 2)];      // (row+8, k+2qk)
                a[mt][2] = ap[4];                   // (row,   k+2qk+8)
                a[mt][3] = ap[8 * (PADH / 2) + 4];  // (row+8, k+2qk+8)
            }
#pragma unroll
            for (int nt = 0; nt < 8; nt++) {
                const uint32_t* bp = Bb_ + (wn * 64 + nt * 8 + qr) * (PADH / 2) + (ks >> 1) + qk;
                uint32_t b[2];
                b[0] = bp[0];
                b[1] = bp[4];
                mma_f16(acc[0][nt], a[0], b);
                mma_f16(acc[1][nt], a[1], b);
            }
        }
        __syncthreads();
    }

#pragma unroll
    for (int mt = 0; mt < 2; mt++) {
        const int mr = m0 + wm * 32 + mt * 16 + qr;
#pragma unroll
        for (int nt = 0; nt < 8; nt++) {
            const int n = n0 + wn * 64 + nt * 8 + qk * 2;
            float b0 = bias1[n], b1 = bias1[n + 1];
            if (bias2) { b0 += bias2[n]; b1 += bias2[n + 1]; }
            *(float2*)&C[(size_t)mr * N + n]       = make_float2(acc[mt][nt][0] + b0, acc[mt][nt][1] + b1);
            *(float2*)&C[(size_t)(mr + 8) * N + n] = make_float2(acc[mt][nt][2] + b0, acc[mt][nt][3] + b1);
        }
    }
}

// ---------------- LayerNorm + LeakyReLU (+ mask): fp32 in, fp16 out ----------------
__global__ __launch_bounds__(256) void ln_lrelu_kernel(
    const float* __restrict__ X, __half* __restrict__ Xh,
    const float* __restrict__ gm, const float* __restrict__ bt,
    const int* __restrict__ lens, int domask)
{
    const int row = blockIdx.x;
    const int tid = threadIdx.x;
    const float4* Xr = (const float4*)(X + (size_t)row * NH);
    float4 v = Xr[tid];
    __shared__ float rs[256], rq[256];
    rs[tid] = v.x + v.y + v.z + v.w;
    rq[tid] = v.x * v.x + v.y * v.y + v.z * v.z + v.w * v.w;
    __syncthreads();
    for (int o = 128; o; o >>= 1) {
        if (tid < o) { rs[tid] += rs[tid + o]; rq[tid] += rq[tid + o]; }
        __syncthreads();
    }
    const float mean = rs[0] * (1.f / NH);
    const float var  = rq[0] * (1.f / NH) - mean * mean;
    const float rstd = rsqrtf(var + 1e-5f);
    float mul = 1.f;
    if (domask) {
        const int b = row >> 9, t = row & 511;
        if (t >= lens[b]) mul = 0.f;
    }
    const int gb = tid * 4;
    float y0 = (v.x - mean) * rstd * gm[gb + 0] + bt[gb + 0];
    float y1 = (v.y - mean) * rstd * gm[gb + 1] + bt[gb + 1];
    float y2 = (v.z - mean) * rstd * gm[gb + 2] + bt[gb + 2];
    float y3 = (v.w - mean) * rstd * gm[gb + 3] + bt[gb + 3];
    y0 = (y0 >= 0.f ? y0 : 0.01f * y0) * mul;
    y1 = (y1 >= 0.f ? y1 : 0.01f * y1) * mul;
    y2 = (y2 >= 0.f ? y2 : 0.01f * y2) * mul;
    y3 = (y3 >= 0.f ? y3 : 0.01f * y3) * mul;
    uint2 o;
    o.x = h2_as_u32(__floats2half2_rn(y0, y1));
    o.y = h2_as_u32(__floats2half2_rn(y2, y3));
    ((uint2*)(Xh + (size_t)row * NH))[tid] = o;
}

// ---------------- persistent tensor-core bidirectional LSTM layer ----------------
#define HPAD 516
#define GPAD 68
__global__ __launch_bounds__(256, 1) void lstm_tc_kernel(
    const float* __restrict__ xp,    // [MT][G8], dir at col offset d*G4
    const float* __restrict__ whh,   // [2][G4][NC] for this layer
    float* __restrict__ out,         // [(b*T+t)][2*NC] fp32 (attention path)
    __half* __restrict__ outh)       // fp16 copy (next GEMM input)
{
    extern __shared__ float sm[];
    float* Hs = sm;                  // 32 x HPAD
    float* Gs = sm + 32 * HPAD;      // 32 x GPAD

    const int tid  = threadIdx.x;
    const int warp = tid >> 5, lane = tid & 31;
    const int qr = lane >> 2, qk = lane & 3;
    const int d    = blockIdx.x >> 5;
    const int j0   = (blockIdx.x & 31) * 16;

    const int ncol = 8 * warp + qr;
    const int jl_w = ncol >> 2, ty_w = ncol & 3;
    const int grow = ty_w * NC + j0 + jl_w;
    const float* wrow = whh + (size_t)d * G4 * NC + (size_t)grow * NC;
    uint32_t b0r[64], b1r[64];
#pragma unroll
    for (int kt = 0; kt < 64; kt++) {
        b0r[kt] = tf32rn(__ldg(wrow + kt * 8 + qk));
        b1r[kt] = tf32rn(__ldg(wrow + kt * 8 + qk + 4));
    }

    const float* xpd = xp + (size_t)d * G4;
    float cst[2] = {0.f, 0.f};
    unsigned gen = 0;

    for (int t = 0; t < Tt; t++) {
        const int tt = d ? (Tt - 1 - t) : t;

        if (t > 0) {
            const float4* src4 = (const float4*)g_hbuf[d * 2 + (t & 1)];
#pragma unroll
            for (int r = 0; r < 16; r++) {
                const int idx = r * 256 + tid;
                float4 v = __ldcg(src4 + idx);
                float4 w;
                w.x = tf32f(v.x); w.y = tf32f(v.y);
                w.z = tf32f(v.z); w.w = tf32f(v.w);
                ((float4*)(Hs + (idx >> 7) * HPAD))[idx & 127] = w;
            }
            __syncthreads();

            float acc[2][4];
#pragma unroll
            for (int mt = 0; mt < 2; mt++)
#pragma unroll
                for (int l = 0; l < 4; l++) acc[mt][l] = 0.f;

#pragma unroll
            for (int kt = 0; kt < 64; kt++) {
                uint32_t b[2] = { b0r[kt], b1r[kt] };
#pragma unroll
                for (int mt = 0; mt < 2; mt++) {
                    const float* hp = Hs + (16 * mt + qr) * HPAD + kt * 8 + qk;
                    uint32_t a[4];
                    a[0] = __float_as_uint(hp[0]);
                    a[1] = __float_as_uint(hp[8 * HPAD]);
                    a[2] = __float_as_uint(hp[4]);
                    a[3] = __float_as_uint(hp[8 * HPAD + 4]);
                    mma_tf32(acc[mt], a, b);
                }
            }
#pragma unroll
            for (int mt = 0; mt < 2; mt++) {
                *(float2*)&Gs[(16 * mt + qr) * GPAD + 8 * warp + 2 * qk] =
                    make_float2(acc[mt][0], acc[mt][1]);
                *(float2*)&Gs[(16 * mt + qr + 8) * GPAD + 8 * warp + 2 * qk] =
                    make_float2(acc[mt][2], acc[mt][3]);
            }
            __syncthreads();
        }

#pragma unroll
        for (int pp = 0; pp < 2; pp++) {
            const int p2 = tid + pp * 256;
            const int b = p2 >> 4, jl = p2 & 15, j = j0 + jl;
            const float* xpr = xpd + ((size_t)b * Tt + tt) * G8;
            float gi = __ldg(xpr + j);
            float gf = __ldg(xpr + NC + j);
            float gg = __ldg(xpr + 2 * NC + j);
            float go = __ldg(xpr + 3 * NC + j);
            if (t > 0) {
                float4 gv = *(const float4*)&Gs[b * GPAD + 4 * jl];
                gi += gv.x; gf += gv.y; gg += gv.z; go += gv.w;
            }
            const float si = 1.f / (1.f + expf(-gi));
            const float sf = 1.f / (1.f + expf(-gf));
            const float sg = tanhf(gg);
            const float so = 1.f / (1.f + expf(-go));
            cst[pp] = sf * cst[pp] + si * sg;
            const float h = so * tanhf(cst[pp]);
            __stcg(&g_hbuf[d * 2 + ((t + 1) & 1)][b * NC + j], h);
            const size_t oidx = ((size_t)b * Tt + tt) * (2 * NC) + d * NC + j;
            out[oidx]  = h;
            outh[oidx] = __float2half_rn(h);
        }

        gridbar(gridDim.x, gen);
    }
}

// ---------------- attention scores ----------------
__global__ __launch_bounds__(256) void scores_kernel(
    const float* __restrict__ h, const float* __restrict__ wu,
    const float* __restrict__ bu, const int* __restrict__ lens,
    float* __restrict__ sc)
{
    const int gid = blockIdx.x * 256 + threadIdx.x;
    const int w = gid >> 5, lane = gid & 31;
    const float* hr = h + (size_t)w * (2 * NC);
    float s = 0.f;
    for (int i = lane; i < 2 * NC; i += 32) s = fmaf(hr[i], wu[i], s);
#pragma unroll
    for (int o = 16; o; o >>= 1) s += __shfl_xor_sync(0xffffffffu, s, o);
    if (lane == 0) {
        const int b = w >> 9, t = w & 511;
        sc[w] = (t < lens[b]) ? (s + bu[0]) : -INFINITY;
    }
}

// ---------------- masked softmax + weighted pool ----------------
__global__ __launch_bounds__(256) void softpool_kernel(
    const float* __restrict__ h, const float* __restrict__ sc,
    float* __restrict__ pooled)
{
    const int b = blockIdx.x, tid = threadIdx.x;
    __shared__ float al[512];
    __shared__ float red[256];
    float m = -INFINITY;
    for (int t = tid; t < 512; t += 256) m = fmaxf(m, sc[b * 512 + t]);
    red[tid] = m; __syncthreads();
    for (int o = 128; o; o >>= 1) {
        if (tid < o) red[tid] = fmaxf(red[tid], red[tid + o]);
        __syncthreads();
    }
    m = red[0]; __syncthreads();
    float s = 0.f;
    for (int t = tid; t < 512; t += 256) {
        const float e = expf(sc[b * 512 + t] - m);
        al[t] = e; s += e;
    }
    red[tid] = s; __syncthreads();
    for (int o = 128; o; o >>= 1) {
        if (tid < o) red[tid] += red[tid + o];
        __syncthreads();
    }
    const float inv = 1.f / red[0];
    __syncthreads();
    for (int d2 = tid; d2 < 2 * NC; d2 += 256) {
        float acc = 0.f;
        for (int t = 0; t < 512; t++)
            acc = fmaf(al[t], h[((size_t)b * 512 + t) * (2 * NC) + d2], acc);
        pooled[b * (2 * NC) + d2] = acc * inv;
    }
}

// ---------------- final classifier ----------------
__global__ __launch_bounds__(256) void final_kernel(
    const float* __restrict__ pooled, const float* __restrict__ Wc,
    const float* __restrict__ bc, float* __restrict__ out)
{
    const int tid = threadIdx.x;
    const int b = tid >> 3, o = tid & 7;
    const float* p = pooled + b * (2 * NC);
    const float* w = Wc + o * (2 * NC);
    float acc = bc[o];
    for (int k = 0; k < 2 * NC; k++) acc = fmaf(p[k], w[k], acc);
    out[b * NOUT + o] = acc;
}

// ---------------- launch ----------------
extern "C" void kernel_launch(void* const* d_in, const int* in_sizes, int n_in,
                              void* d_out, int out_size)
{
    const float* x    = (const float*)d_in[0];
    const int*   lens = (const int*)  d_in[1];
    const float* W1   = (const float*)d_in[2];
    const float* b1   = (const float*)d_in[3];
    const float* g1   = (const float*)d_in[4];
    const float* be1  = (const float*)d_in[5];
    const float* W2   = (const float*)d_in[6];
    const float* b2   = (const float*)d_in[7];
    const float* g2   = (const float*)d_in[8];
    const float* be2  = (const float*)d_in[9];
    const float* wih  = (const float*)d_in[10];
    const float* whh  = (const float*)d_in[11];
    const float* bih  = (const float*)d_in[12];
    const float* bhh  = (const float*)d_in[13];
    const float* wu   = (const float*)d_in[14];
    const float* bu   = (const float*)d_in[15];
    const float* Wc   = (const float*)d_in[16];
    const float* bc   = (const float*)d_in[17];
    float* out = (float*)d_out;

    float  *h1, *h2, *xpb, *l0, *l1, *sc, *pooled;
    __half *xh, *h1h, *h2h, *l0h, *w1h, *w2h, *wihh;
    cudaGetSymbolAddress((void**)&h1, g_h1);
    cudaGetSymbolAddress((void**)&h2, g_h2);
    cudaGetSymbolAddress((void**)&xpb, g_xp);
    cudaGetSymbolAddress((void**)&l0, g_l0);
    cudaGetSymbolAddress((void**)&l1, g_l1);
    cudaGetSymbolAddress((void**)&sc, g_sc);
    cudaGetSymbolAddress((void**)&pooled, g_pooled);
    cudaGetSymbolAddress((void**)&xh, g_xh);
    cudaGetSymbolAddress((void**)&h1h, g_h1h);
    cudaGetSymbolAddress((void**)&h2h, g_h2h);
    cudaGetSymbolAddress((void**)&l0h, g_l0h);
    cudaGetSymbolAddress((void**)&w1h, g_w1h);
    cudaGetSymbolAddress((void**)&w2h, g_w2h);
    cudaGetSymbolAddress((void**)&wihh, g_wihh);

    const int lstm_smem = (32 * HPAD + 32 * GPAD) * 4;
    cudaFuncSetAttribute(lstm_tc_kernel,
                         cudaFuncAttributeMaxDynamicSharedMemorySize, lstm_smem);

    // one-shot fp32 -> fp16 operand conversion
    cvt_f16_kernel<<<(MT * FDim / 4 + 255) / 256, 256>>>((const float4*)x, (uint2*)xh, MT * FDim / 4);
    cvt_f16_kernel<<<(NH * FDim / 4 + 255) / 256, 256>>>((const float4*)W1, (uint2*)w1h, NH * FDim / 4);
    cvt_f16_kernel<<<(NH * NH / 4 + 255) / 256, 256>>>((const float4*)W2, (uint2*)w2h, NH * NH / 4);
    cvt_f16_kernel<<<(2 * G8 * NH / 4 + 255) / 256, 256>>>((const float4*)wih, (uint2*)wihh, 2 * G8 * NH / 4);

    // MLP
    gemm_f16_kernel<<<dim3(NH / 128, MT / 128), 256>>>(xh, w1h, b1, nullptr, h1, MT, NH, FDim);
    ln_lrelu_kernel<<<MT, 256>>>(h1, h1h, g1, be1, nullptr, 0);
    gemm_f16_kernel<<<dim3(NH / 128, MT / 128), 256>>>(h1h, w2h, b2, nullptr, h2, MT, NH, NH);
    ln_lrelu_kernel<<<MT, 256>>>(h2, h2h, g2, be2, lens, 1);

    // 2 bidirectional LSTM layers
    const __half* linh = h2h;
    float*  louts[2]  = { l0, l1 };
    __half* louths[2] = { l0h, l0h };   // layer-1 half copy is never read
    for (int l = 0; l < 2; l++) {
        gemm_f16_kernel<<<dim3(G8 / 128, MT / 128), 256>>>(
            linh, wihh + (size_t)l * G8 * NH,
            bih + (size_t)l * G8, bhh + (size_t)l * G8,
            xpb, MT, G8, NH);
        reset_bar_kernel<<<1, 1>>>();
        lstm_tc_kernel<<<64, 256, lstm_smem>>>(xpb, whh + (size_t)l * 2 * G4 * NC,
                                               louts[l], louths[l]);
        linh = louths[l];
    }

    // attention + head
    scores_kernel<<<MT / 8, 256>>>(l1, wu, bu, lens, sc);
    softpool_kernel<<<Bq, 256>>>(l1, sc, pooled);
    final_kernel<<<1, 256>>>(pooled, Wc, bc, out);
}

// round 12
// speedup vs baseline: 3.8291x; 1.3919x over previous
#include <cuda_runtime.h>
#include <cuda_fp16.h>
#include <math.h>
#include <stdint.h>
#include <string.h>

#define Bq   32
#define Tt   512
#define FDim 256
#define NH   1024
#define NC   512
#define G4   2048      // 4*NC
#define G8   4096      // 2 dirs * 4*NC
#define NOUT 8
#define MT   (Bq*Tt)   // 16384 rows

// ---------------- device scratch ----------------
__device__ float  g_h1[(size_t)MT*NH];
__device__ float  g_h2[(size_t)MT*NH];
__device__ float  g_xp[(size_t)MT*G8];         // [(b*T+t)][dir*G4 + g]
__device__ float  g_l1[(size_t)MT*2*NC];
__device__ __half g_hbufh[4][Bq*NC];           // [dir*2+parity][b][j], fp16 h state
__device__ float  g_sc[Bq*Tt];
__device__ float  g_pooled[Bq*2*NC];
__device__ __half g_xh[(size_t)MT*FDim];
__device__ __half g_h1h[(size_t)MT*NH];
__device__ __half g_h2h[(size_t)MT*NH];
__device__ __half g_l0h[(size_t)MT*2*NC];
__device__ __half g_w1h[(size_t)NH*FDim];
__device__ __half g_w2h[(size_t)NH*NH];
__device__ __half g_wihh[(size_t)2*G8*NH];
__device__ unsigned g_bar_arrive;
__device__ unsigned g_bar_gen;

// ---------------- grid barrier (release/acquire, no membar) ----------------
__device__ __forceinline__ void gridbar(unsigned nb, unsigned &gen) {
    __syncthreads();
    if (threadIdx.x == 0) {
        gen++;
        unsigned prev;
        asm volatile("atom.add.release.gpu.u32 %0, [%1], 1;"
                     : "=r"(prev) : "l"(&g_bar_arrive) : "memory");
        if (prev == nb * gen - 1u) {
            asm volatile("st.release.gpu.u32 [%0], %1;"
                         :: "l"(&g_bar_gen), "r"(gen) : "memory");
        } else {
            unsigned cur;
            do {
                asm volatile("ld.acquire.gpu.u32 %0, [%1];"
                             : "=r"(cur) : "l"(&g_bar_gen) : "memory");
            } while (cur < gen);
        }
    }
    __syncthreads();
}

__global__ void reset_bar_kernel() {
    g_bar_arrive = 0u;
    g_bar_gen = 0u;
}

// ---------------- helpers ----------------
__device__ __forceinline__ unsigned su32(const void* p) {
    unsigned r;
    asm("{.reg .u64 t; cvta.to.shared.u64 t, %1; cvt.u32.u64 %0, t;}" : "=r"(r) : "l"(p));
    return r;
}
__device__ __forceinline__ void cp16(unsigned s, const void* g) {
    asm volatile("cp.async.cg.shared.global [%0], [%1], 16;\n" :: "r"(s), "l"(g));
}
__device__ __forceinline__ uint32_t h2_as_u32(__half2 h) {
    __half2_raw r = *(__half2_raw*)&h;
    return (uint32_t)r.x | ((uint32_t)r.y << 16);
}
__device__ __forceinline__ float fexp(float x) {
    float r;
    asm("ex2.approx.f32 %0, %1;" : "=f"(r) : "f"(x * 1.4426950408889634f));
    return r;
}
__device__ __forceinline__ float fsig(float x) {
    return __fdividef(1.f, 1.f + fexp(-x));
}
__device__ __forceinline__ float ftanh(float x) {
    const float xx = fminf(fmaxf(x, -15.f), 15.f);
    const float e = fexp(2.f * xx);
    return __fdividef(e - 1.f, e + 1.f);
}
__device__ __forceinline__ void mma_f16(float (&c)[4], const uint32_t (&a)[4], const uint32_t (&b)[2]) {
    asm volatile("mma.sync.aligned.m16n8k16.row.col.f32.f16.f16.f32 "
        "{%0,%1,%2,%3}, {%4,%5,%6,%7}, {%8,%9}, {%0,%1,%2,%3};\n"
        : "+f"(c[0]), "+f"(c[1]), "+f"(c[2]), "+f"(c[3])
        : "r"(a[0]), "r"(a[1]), "r"(a[2]), "r"(a[3]), "r"(b[0]), "r"(b[1]));
}

// ---------------- elementwise fp32 -> fp16 ----------------
__global__ __launch_bounds__(256) void cvt_f16_kernel(
    const float4* __restrict__ src, uint2* __restrict__ dst, int n4)
{
    const int i = blockIdx.x * 256 + threadIdx.x;
    if (i < n4) {
        float4 v = src[i];
        uint2 o;
        o.x = h2_as_u32(__floats2half2_rn(v.x, v.y));
        o.y = h2_as_u32(__floats2half2_rn(v.z, v.w));
        dst[i] = o;
    }
}

// ---------------- fp16 GEMM: C = A[M,K]*W[N,K]^T + b1 (+b2), fp32 accum/out ----------------
#define PADH 40
__global__ __launch_bounds__(256) void gemm_f16_kernel(
    const __half* __restrict__ A, const __half* __restrict__ W,
    const float* __restrict__ bias1, const float* __restrict__ bias2,
    float* __restrict__ C, int M, int N, int K)
{
    __shared__ __half As[2][128 * PADH];
    __shared__ __half Ws[2][128 * PADH];
    const int tid  = threadIdx.x;
    const int warp = tid >> 5, lane = tid & 31;
    const int wm = warp & 3, wn = warp >> 2;
    const int qr = lane >> 2, qk = lane & 3;
    const int m0 = blockIdx.y * 128;
    const int n0 = blockIdx.x * 128;

    const int ca = tid * 2, cb = ca + 1;
    const int ra = ca >> 2, ka = (ca & 3) * 8;
    const int rb = cb >> 2, kb = (cb & 3) * 8;

    const __half* Ag = A + (size_t)m0 * K;
    const __half* Wg = W + (size_t)n0 * K;

    const unsigned sAa = su32(&As[0][ra * PADH + ka]);
    const unsigned sAb = su32(&As[0][rb * PADH + kb]);
    const unsigned sWa = su32(&Ws[0][ra * PADH + ka]);
    const unsigned sWb = su32(&Ws[0][rb * PADH + kb]);
    const unsigned stgB = 128 * PADH * 2;

    float acc[2][8][4];
#pragma unroll
    for (int i = 0; i < 2; i++)
#pragma unroll
        for (int j = 0; j < 8; j++)
#pragma unroll
            for (int l = 0; l < 4; l++) acc[i][j][l] = 0.f;

    const int nk = K >> 5;

    cp16(sAa, Ag + (size_t)ra * K + ka);
    cp16(sAb, Ag + (size_t)rb * K + kb);
    cp16(sWa, Wg + (size_t)ra * K + ka);
    cp16(sWb, Wg + (size_t)rb * K + kb);
    asm volatile("cp.async.commit_group;\n");

    for (int kt = 0; kt < nk; kt++) {
        if (kt + 1 < nk) {
            const int k0 = (kt + 1) * 32;
            const unsigned so = ((kt + 1) & 1) * stgB;
            cp16(sAa + so, Ag + (size_t)ra * K + k0 + ka);
            cp16(sAb + so, Ag + (size_t)rb * K + k0 + kb);
            cp16(sWa + so, Wg + (size_t)ra * K + k0 + ka);
            cp16(sWb + so, Wg + (size_t)rb * K + k0 + kb);
            asm volatile("cp.async.commit_group;\n");
            asm volatile("cp.async.wait_group 1;\n");
        } else {
            asm volatile("cp.async.wait_group 0;\n");
        }
        __syncthreads();

        const uint32_t* Ab_ = (const uint32_t*)&As[kt & 1][0];
        const uint32_t* Bb_ = (const uint32_t*)&Ws[kt & 1][0];
#pragma unroll
        for (int ks = 0; ks < 32; ks += 16) {
            uint32_t a[2][4];
#pragma unroll
            for (int mt = 0; mt < 2; mt++) {
                const uint32_t* ap = Ab_ + (wm * 32 + mt * 16 + qr) * (PADH / 2) + (ks >> 1) + qk;
                a[mt][0] = ap[0];
                a[mt][1] = ap[8 * (PADH / 2)];
                a[mt][2] = ap[4];
                a[mt][3] = ap[8 * (PADH / 2) + 4];
            }
#pragma unroll
            for (int nt = 0; nt < 8; nt++) {
                const uint32_t* bp = Bb_ + (wn * 64 + nt * 8 + qr) * (PADH / 2) + (ks >> 1) + qk;
                uint32_t b[2];
                b[0] = bp[0];
                b[1] = bp[4];
                mma_f16(acc[0][nt], a[0], b);
                mma_f16(acc[1][nt], a[1], b);
            }
        }
        __syncthreads();
    }

#pragma unroll
    for (int mt = 0; mt < 2; mt++) {
        const int mr = m0 + wm * 32 + mt * 16 + qr;
#pragma unroll
        for (int nt = 0; nt < 8; nt++) {
            const int n = n0 + wn * 64 + nt * 8 + qk * 2;
            float b0 = bias1[n], b1 = bias1[n + 1];
            if (bias2) { b0 += bias2[n]; b1 += bias2[n + 1]; }
            *(float2*)&C[(size_t)mr * N + n]       = make_float2(acc[mt][nt][0] + b0, acc[mt][nt][1] + b1);
            *(float2*)&C[(size_t)(mr + 8) * N + n] = make_float2(acc[mt][nt][2] + b0, acc[mt][nt][3] + b1);
        }
    }
}

// ---------------- LayerNorm + LeakyReLU (+ mask): fp32 in, fp16 out ----------------
__global__ __launch_bounds__(256) void ln_lrelu_kernel(
    const float* __restrict__ X, __half* __restrict__ Xh,
    const float* __restrict__ gm, const float* __restrict__ bt,
    const int* __restrict__ lens, int domask)
{
    const int row = blockIdx.x;
    const int tid = threadIdx.x;
    const float4* Xr = (const float4*)(X + (size_t)row * NH);
    float4 v = Xr[tid];
    __shared__ float rs[256], rq[256];
    rs[tid] = v.x + v.y + v.z + v.w;
    rq[tid] = v.x * v.x + v.y * v.y + v.z * v.z + v.w * v.w;
    __syncthreads();
    for (int o = 128; o; o >>= 1) {
        if (tid < o) { rs[tid] += rs[tid + o]; rq[tid] += rq[tid + o]; }
        __syncthreads();
    }
    const float mean = rs[0] * (1.f / NH);
    const float var  = rq[0] * (1.f / NH) - mean * mean;
    const float rstd = rsqrtf(var + 1e-5f);
    float mul = 1.f;
    if (domask) {
        const int b = row >> 9, t = row & 511;
        if (t >= lens[b]) mul = 0.f;
    }
    const int gb = tid * 4;
    float y0 = (v.x - mean) * rstd * gm[gb + 0] + bt[gb + 0];
    float y1 = (v.y - mean) * rstd * gm[gb + 1] + bt[gb + 1];
    float y2 = (v.z - mean) * rstd * gm[gb + 2] + bt[gb + 2];
    float y3 = (v.w - mean) * rstd * gm[gb + 3] + bt[gb + 3];
    y0 = (y0 >= 0.f ? y0 : 0.01f * y0) * mul;
    y1 = (y1 >= 0.f ? y1 : 0.01f * y1) * mul;
    y2 = (y2 >= 0.f ? y2 : 0.01f * y2) * mul;
    y3 = (y3 >= 0.f ? y3 : 0.01f * y3) * mul;
    uint2 o;
    o.x = h2_as_u32(__floats2half2_rn(y0, y1));
    o.y = h2_as_u32(__floats2half2_rn(y2, y3));
    ((uint2*)(Xh + (size_t)row * NH))[tid] = o;
}

// ---------------- persistent fp16 tensor-core bidirectional LSTM layer ----------------
// 64 blocks: d = blk>>5, block owns 16 hidden units (x4 gates = 64 N-cols).
// whh fp16 fragments in 64 registers; h state fp16 in smem (row stride 520 halves).
#define HPADH 520
#define GPAD  68
__global__ __launch_bounds__(256, 1) void lstm_tc_kernel(
    const float* __restrict__ xp,    // [MT][G8], dir at col offset d*G4
    const float* __restrict__ whh,   // [2][G4][NC] for this layer
    float* __restrict__ out,         // optional fp32 out [(b*T+t)][2*NC]
    __half* __restrict__ outh)       // optional fp16 out
{
    extern __shared__ char smraw[];
    __half* Hs = (__half*)smraw;                   // 32 x HPADH halves
    float*  Gs = (float*)(smraw + 32 * HPADH * 2); // 32 x GPAD floats

    const int tid  = threadIdx.x;
    const int warp = tid >> 5, lane = tid & 31;
    const int qr = lane >> 2, qk = lane & 3;
    const int d    = blockIdx.x >> 5;
    const int j0   = (blockIdx.x & 31) * 16;

    // B fragments (fp16): warp covers N-cols 8w..8w+7; fragment n-index = qr
    const int ncol = 8 * warp + qr;
    const int jl_w = ncol >> 2, ty_w = ncol & 3;
    const int grow = ty_w * NC + j0 + jl_w;
    const float* wrow = whh + (size_t)d * G4 * NC + (size_t)grow * NC;
    uint32_t b0r[32], b1r[32];
#pragma unroll
    for (int kt = 0; kt < 32; kt++) {
        const float w0 = __ldg(wrow + kt * 16 + 2 * qk);
        const float w1 = __ldg(wrow + kt * 16 + 2 * qk + 1);
        const float w2 = __ldg(wrow + kt * 16 + 2 * qk + 8);
        const float w3 = __ldg(wrow + kt * 16 + 2 * qk + 9);
        b0r[kt] = h2_as_u32(__floats2half2_rn(w0, w1));
        b1r[kt] = h2_as_u32(__floats2half2_rn(w2, w3));
    }

    const float* xpd = xp + (size_t)d * G4;
    float cst[2] = {0.f, 0.f};
    unsigned gen = 0;

    for (int t = 0; t < Tt; t++) {
        const int tt = d ? (Tt - 1 - t) : t;

        if (t > 0) {
            // stage fp16 h_{t-1}: 32 rows x 512 halves = 2048 uint4
            const uint4* src = (const uint4*)g_hbufh[d * 2 + (t & 1)];
#pragma unroll
            for (int r = 0; r < 8; r++) {
                const int idx = r * 256 + tid;
                uint4 v = __ldcg(src + idx);
                const int row = idx >> 6, col = idx & 63;
                *(uint4*)(Hs + row * HPADH + col * 8) = v;
            }
            __syncthreads();

            float acc[2][4];
#pragma unroll
            for (int mt = 0; mt < 2; mt++)
#pragma unroll
                for (int l = 0; l < 4; l++) acc[mt][l] = 0.f;

            const uint32_t* Hs32 = (const uint32_t*)Hs;
#pragma unroll
            for (int kt = 0; kt < 32; kt++) {
                uint32_t b[2] = { b0r[kt], b1r[kt] };
#pragma unroll
                for (int mt = 0; mt < 2; mt++) {
                    const uint32_t* ap = Hs32 + (16 * mt + qr) * (HPADH / 2) + kt * 8 + qk;
                    uint32_t a[4];
                    a[0] = ap[0];
                    a[1] = ap[8 * (HPADH / 2)];
                    a[2] = ap[4];
                    a[3] = ap[8 * (HPADH / 2) + 4];
                    mma_f16(acc[mt], a, b);
                }
            }
#pragma unroll
            for (int mt = 0; mt < 2; mt++) {
                *(float2*)&Gs[(16 * mt + qr) * GPAD + 8 * warp + 2 * qk] =
                    make_float2(acc[mt][0], acc[mt][1]);
                *(float2*)&Gs[(16 * mt + qr + 8) * GPAD + 8 * warp + 2 * qk] =
                    make_float2(acc[mt][2], acc[mt][3]);
            }
            __syncthreads();
        }

#pragma unroll
        for (int pp = 0; pp < 2; pp++) {
            const int p2 = tid + pp * 256;
            const int b = p2 >> 4, jl = p2 & 15, j = j0 + jl;
            const float* xpr = xpd + ((size_t)b * Tt + tt) * G8;
            float gi = __ldg(xpr + j);
            float gf = __ldg(xpr + NC + j);
            float gg = __ldg(xpr + 2 * NC + j);
            float go = __ldg(xpr + 3 * NC + j);
            if (t > 0) {
                float4 gv = *(const float4*)&Gs[b * GPAD + 4 * jl];
                gi += gv.x; gf += gv.y; gg += gv.z; go += gv.w;
            }
            const float si = fsig(gi);
            const float sf = fsig(gf);
            const float sg = ftanh(gg);
            const float so = fsig(go);
            cst[pp] = sf * cst[pp] + si * sg;
            const float h = so * ftanh(cst[pp]);
            g_hbufh[d * 2 + ((t + 1) & 1)][b * NC + j] = __float2half_rn(h);
            const size_t oidx = ((size_t)b * Tt + tt) * (2 * NC) + d * NC + j;
            if (out)  out[oidx]  = h;
            if (outh) outh[oidx] = __float2half_rn(h);
        }

        gridbar(gridDim.x, gen);
    }
}

// ---------------- attention scores ----------------
__global__ __launch_bounds__(256) void scores_kernel(
    const float* __restrict__ h, const float* __restrict__ wu,
    const float* __restrict__ bu, const int* __restrict__ lens,
    float* __restrict__ sc)
{
    const int gid = blockIdx.x * 256 + threadIdx.x;
    const int w = gid >> 5, lane = gid & 31;
    const float* hr = h + (size_t)w * (2 * NC);
    float s = 0.f;
    for (int i = lane; i < 2 * NC; i += 32) s = fmaf(hr[i], wu[i], s);
#pragma unroll
    for (int o = 16; o; o >>= 1) s += __shfl_xor_sync(0xffffffffu, s, o);
    if (lane == 0) {
        const int b = w >> 9, t = w & 511;
        sc[w] = (t < lens[b]) ? (s + bu[0]) : -INFINITY;
    }
}

// ---------------- masked softmax + weighted pool ----------------
__global__ __launch_bounds__(256) void softpool_kernel(
    const float* __restrict__ h, const float* __restrict__ sc,
    float* __restrict__ pooled)
{
    const int b = blockIdx.x, tid = threadIdx.x;
    __shared__ float al[512];
    __shared__ float red[256];
    float m = -INFINITY;
    for (int t = tid; t < 512; t += 256) m = fmaxf(m, sc[b * 512 + t]);
    red[tid] = m; __syncthreads();
    for (int o = 128; o; o >>= 1) {
        if (tid < o) red[tid] = fmaxf(red[tid], red[tid + o]);
        __syncthreads();
    }
    m = red[0]; __syncthreads();
    float s = 0.f;
    for (int t = tid; t < 512; t += 256) {
        const float e = expf(sc[b * 512 + t] - m);
        al[t] = e; s += e;
    }
    red[tid] = s; __syncthreads();
    for (int o = 128; o; o >>= 1) {
        if (tid < o) red[tid] += red[tid + o];
        __syncthreads();
    }
    const float inv = 1.f / red[0];
    __syncthreads();
    for (int d2 = tid; d2 < 2 * NC; d2 += 256) {
        float acc = 0.f;
        for (int t = 0; t < 512; t++)
            acc = fmaf(al[t], h[((size_t)b * 512 + t) * (2 * NC) + d2], acc);
        pooled[b * (2 * NC) + d2] = acc * inv;
    }
}

// ---------------- final classifier ----------------
__global__ __launch_bounds__(256) void final_kernel(
    const float* __restrict__ pooled, const float* __restrict__ Wc,
    const float* __restrict__ bc, float* __restrict__ out)
{
    const int tid = threadIdx.x;
    const int b = tid >> 3, o = tid & 7;
    const float* p = pooled + b * (2 * NC);
    const float* w = Wc + o * (2 * NC);
    float acc = bc[o];
    for (int k = 0; k < 2 * NC; k++) acc = fmaf(p[k], w[k], acc);
    out[b * NOUT + o] = acc;
}

// ---------------- launch ----------------
extern "C" void kernel_launch(void* const* d_in, const int* in_sizes, int n_in,
                              void* d_out, int out_size)
{
    const float* x    = (const float*)d_in[0];
    const int*   lens = (const int*)  d_in[1];
    const float* W1   = (const float*)d_in[2];
    const float* b1   = (const float*)d_in[3];
    const float* g1   = (const float*)d_in[4];
    const float* be1  = (const float*)d_in[5];
    const float* W2   = (const float*)d_in[6];
    const float* b2   = (const float*)d_in[7];
    const float* g2   = (const float*)d_in[8];
    const float* be2  = (const float*)d_in[9];
    const float* wih  = (const float*)d_in[10];
    const float* whh  = (const float*)d_in[11];
    const float* bih  = (const float*)d_in[12];
    const float* bhh  = (const float*)d_in[13];
    const float* wu   = (const float*)d_in[14];
    const float* bu   = (const float*)d_in[15];
    const float* Wc   = (const float*)d_in[16];
    const float* bc   = (const float*)d_in[17];
    float* out = (float*)d_out;

    float  *h1, *h2, *xpb, *l1, *sc, *pooled;
    __half *xh, *h1h, *h2h, *l0h, *w1h, *w2h, *wihh;
    cudaGetSymbolAddress((void**)&h1, g_h1);
    cudaGetSymbolAddress((void**)&h2, g_h2);
    cudaGetSymbolAddress((void**)&xpb, g_xp);
    cudaGetSymbolAddress((void**)&l1, g_l1);
    cudaGetSymbolAddress((void**)&sc, g_sc);
    cudaGetSymbolAddress((void**)&pooled, g_pooled);
    cudaGetSymbolAddress((void**)&xh, g_xh);
    cudaGetSymbolAddress((void**)&h1h, g_h1h);
    cudaGetSymbolAddress((void**)&h2h, g_h2h);
    cudaGetSymbolAddress((void**)&l0h, g_l0h);
    cudaGetSymbolAddress((void**)&w1h, g_w1h);
    cudaGetSymbolAddress((void**)&w2h, g_w2h);
    cudaGetSymbolAddress((void**)&wihh, g_wihh);

    const int lstm_smem = 32 * HPADH * 2 + 32 * GPAD * 4;
    cudaFuncSetAttribute(lstm_tc_kernel,
                         cudaFuncAttributeMaxDynamicSharedMemorySize, lstm_smem);

    // one-shot fp32 -> fp16 operand conversion
    cvt_f16_kernel<<<(MT * FDim / 4 + 255) / 256, 256>>>((const float4*)x, (uint2*)xh, MT * FDim / 4);
    cvt_f16_kernel<<<(NH * FDim / 4 + 255) / 256, 256>>>((const float4*)W1, (uint2*)w1h, NH * FDim / 4);
    cvt_f16_kernel<<<(NH * NH / 4 + 255) / 256, 256>>>((const float4*)W2, (uint2*)w2h, NH * NH / 4);
    cvt_f16_kernel<<<(2 * G8 * NH / 4 + 255) / 256, 256>>>((const float4*)wih, (uint2*)wihh, 2 * G8 * NH / 4);

    // MLP
    gemm_f16_kernel<<<dim3(NH / 128, MT / 128), 256>>>(xh, w1h, b1, nullptr, h1, MT, NH, FDim);
    ln_lrelu_kernel<<<MT, 256>>>(h1, h1h, g1, be1, nullptr, 0);
    gemm_f16_kernel<<<dim3(NH / 128, MT / 128), 256>>>(h1h, w2h, b2, nullptr, h2, MT, NH, NH);
    ln_lrelu_kernel<<<MT, 256>>>(h2, h2h, g2, be2, lens, 1);

    // LSTM layer 0: fp16 out only (feeds layer-1 GEMM)
    gemm_f16_kernel<<<dim3(G8 / 128, MT / 128), 256>>>(
        h2h, wihh, bih, bhh, xpb, MT, G8, NH);
    reset_bar_kernel<<<1, 1>>>();
    lstm_tc_kernel<<<64, 256, lstm_smem>>>(xpb, whh, nullptr, l0h);

    // LSTM layer 1: fp32 out only (feeds attention)
    gemm_f16_kernel<<<dim3(G8 / 128, MT / 128), 256>>>(
        l0h, wihh + (size_t)G8 * NH,
        bih + G8, bhh + G8, xpb, MT, G8, NH);
    reset_bar_kernel<<<1, 1>>>();
    lstm_tc_kernel<<<64, 256, lstm_smem>>>(xpb, whh + (size_t)2 * G4 * NC, l1, nullptr);

    // attention + head
    scores_kernel<<<MT / 8, 256>>>(l1, wu, bu, lens, sc);
    softpool_kernel<<<Bq, 256>>>(l1, sc, pooled);
    final_kernel<<<1, 256>>>(pooled, Wc, bc, out);
}